// round 2
// baseline (speedup 1.0000x reference)
#include <cuda_runtime.h>
#include <math.h>

#define D_MODEL 1024
#define NUM_HEADS 16
#define DK 64
#define HALF 32
#define BB 4
#define SS 2048
#define MM (BB * SS)           // 8192 tokens
#define LOG2_THETA 13.287712379549449f   // log2(10000)

// ---------------- scratch (device globals: no allocation allowed) ----------
__device__ float g_q[(size_t)MM * D_MODEL];
__device__ float g_k[(size_t)MM * D_MODEL];
__device__ float g_v[(size_t)MM * D_MODEL];
__device__ float g_att[(size_t)MM * D_MODEL];

// ---------------------------------------------------------------------------
// SGEMM (NT): C[M,N] = A[M,K] * B[N,K]^T   (both operands K-contiguous)
// 128x128 block tile, K-step 8, 256 threads, 8x8 micro-tile.
// ---------------------------------------------------------------------------
__global__ void __launch_bounds__(256) sgemm_nt_kernel(
    const float* __restrict__ A, const float* __restrict__ B,
    float* __restrict__ C, int Mdim, int Ndim, int Kdim)
{
    __shared__ float As[8][128];
    __shared__ float Bs[8][128];

    const int tid  = threadIdx.x;
    const int row0 = blockIdx.y * 128;
    const int col0 = blockIdx.x * 128;
    const int tx   = tid & 15;
    const int ty   = tid >> 4;

    const int lr = tid >> 1;          // 0..127: tile row to load
    const int lk = (tid & 1) * 4;     // 0 or 4: k sub-chunk

    const float* Ap = A + (size_t)(row0 + lr) * Kdim + lk;
    const float* Bp = B + (size_t)(col0 + lr) * Kdim + lk;

    float acc[8][8];
#pragma unroll
    for (int i = 0; i < 8; ++i)
#pragma unroll
        for (int j = 0; j < 8; ++j) acc[i][j] = 0.f;

    for (int k0 = 0; k0 < Kdim; k0 += 8) {
        float4 av = *(const float4*)(Ap + k0);
        float4 bv = *(const float4*)(Bp + k0);
        __syncthreads();
        As[lk + 0][lr] = av.x; As[lk + 1][lr] = av.y;
        As[lk + 2][lr] = av.z; As[lk + 3][lr] = av.w;
        Bs[lk + 0][lr] = bv.x; Bs[lk + 1][lr] = bv.y;
        Bs[lk + 2][lr] = bv.z; Bs[lk + 3][lr] = bv.w;
        __syncthreads();

#pragma unroll
        for (int kk = 0; kk < 8; ++kk) {
            float4 a0 = *(const float4*)&As[kk][ty * 8];
            float4 a1 = *(const float4*)&As[kk][ty * 8 + 4];
            float4 b0 = *(const float4*)&Bs[kk][tx * 8];
            float4 b1 = *(const float4*)&Bs[kk][tx * 8 + 4];
            float a[8] = {a0.x, a0.y, a0.z, a0.w, a1.x, a1.y, a1.z, a1.w};
            float b[8] = {b0.x, b0.y, b0.z, b0.w, b1.x, b1.y, b1.z, b1.w};
#pragma unroll
            for (int i = 0; i < 8; ++i)
#pragma unroll
                for (int j = 0; j < 8; ++j)
                    acc[i][j] = fmaf(a[i], b[j], acc[i][j]);
        }
    }

#pragma unroll
    for (int i = 0; i < 8; ++i) {
        float* cp = C + (size_t)(row0 + ty * 8 + i) * Ndim + col0 + tx * 8;
        *(float4*)(cp)     = make_float4(acc[i][0], acc[i][1], acc[i][2], acc[i][3]);
        *(float4*)(cp + 4) = make_float4(acc[i][4], acc[i][5], acc[i][6], acc[i][7]);
    }
}

// ---------------------------------------------------------------------------
// RoPE: in-place on q and k. One thread per (token m, head h, freq i).
// ---------------------------------------------------------------------------
__global__ void __launch_bounds__(256) rope_kernel(
    float* __restrict__ q, float* __restrict__ k, const int* __restrict__ pos)
{
    const int idx = blockIdx.x * blockDim.x + threadIdx.x;  // < MM*H*HALF
    const int i = idx & (HALF - 1);
    const int h = (idx >> 5) & (NUM_HEADS - 1);
    const int m = idx >> 9;
    const int s = m & (SS - 1);

    const float p = (float)pos[s];
    const float inv_freq = exp2f(-(float)i * (LOG2_THETA / (float)HALF));
    float sn, cs;
    sincosf(p * inv_freq, &sn, &cs);

    const size_t base = (size_t)m * D_MODEL + h * DK + 2 * i;

    float2 qv = *(float2*)(q + base);
    *(float2*)(q + base) = make_float2(qv.x * cs - qv.y * sn, qv.x * sn + qv.y * cs);
    float2 kv = *(float2*)(k + base);
    *(float2*)(k + base) = make_float2(kv.x * cs - kv.y * sn, kv.x * sn + kv.y * cs);
}

// ---------------------------------------------------------------------------
// Flash attention (causal), fp32. Block = one (b, h, 64-row q tile).
// 256 threads as 16x16; each thread owns a 4x4 micro-tile.
// Q/K tiles stored transposed [d][row] with XOR swizzle; P reuses K buffer.
// Static smem = 3 * 16KB = 48KB.
// ---------------------------------------------------------------------------
#define SWZ(x) ((((x) >> 2) & 7) << 2)

__global__ void __launch_bounds__(256) attn_kernel(
    const float* __restrict__ Q, const float* __restrict__ K,
    const float* __restrict__ V, float* __restrict__ O)
{
    __shared__ float Qs[64 * 64];   // [d][row^swz(d)]
    __shared__ float KPs[64 * 64];  // K tile [d][col^swz(d)], then P tile [kcol][row^swz]
    __shared__ float Vs[64 * 64];   // [krow][d]

    const int qt = blockIdx.x;
    const int h  = blockIdx.y;
    const int b  = blockIdx.z;
    const int tid = threadIdx.x;
    const int tx = tid & 15;
    const int ty = tid >> 4;

    const float* qbase = Q + ((size_t)(b * SS) + qt * 64) * D_MODEL + h * DK;

    // load Q tile transposed + swizzled
#pragma unroll
    for (int it = 0; it < 4; ++it) {
        int f4  = tid + it * 256;
        int row = f4 >> 4;
        int c4  = (f4 & 15) * 4;
        float4 vq = *(const float4*)(qbase + (size_t)row * D_MODEL + c4);
        Qs[(c4 + 0) * 64 + (row ^ SWZ(c4 + 0))] = vq.x;
        Qs[(c4 + 1) * 64 + (row ^ SWZ(c4 + 1))] = vq.y;
        Qs[(c4 + 2) * 64 + (row ^ SWZ(c4 + 2))] = vq.z;
        Qs[(c4 + 3) * 64 + (row ^ SWZ(c4 + 3))] = vq.w;
    }

    float m_i[4], l_i[4], acc[4][4];
#pragma unroll
    for (int i = 0; i < 4; ++i) {
        m_i[i] = -1e30f; l_i[i] = 0.f;
#pragma unroll
        for (int j = 0; j < 4; ++j) acc[i][j] = 0.f;
    }

    const int qrow0 = qt * 64;

    for (int kt = 0; kt <= qt; ++kt) {
        __syncthreads();  // prior iter's P/V reads complete before overwrite

        const float* kbase = K + ((size_t)(b * SS) + kt * 64) * D_MODEL + h * DK;
        const float* vbase = V + ((size_t)(b * SS) + kt * 64) * D_MODEL + h * DK;
#pragma unroll
        for (int it = 0; it < 4; ++it) {
            int f4  = tid + it * 256;
            int row = f4 >> 4;
            int c4  = (f4 & 15) * 4;
            float4 kv = *(const float4*)(kbase + (size_t)row * D_MODEL + c4);
            KPs[(c4 + 0) * 64 + (row ^ SWZ(c4 + 0))] = kv.x;
            KPs[(c4 + 1) * 64 + (row ^ SWZ(c4 + 1))] = kv.y;
            KPs[(c4 + 2) * 64 + (row ^ SWZ(c4 + 2))] = kv.z;
            KPs[(c4 + 3) * 64 + (row ^ SWZ(c4 + 3))] = kv.w;
            float4 vv = *(const float4*)(vbase + (size_t)row * D_MODEL + c4);
            *(float4*)&Vs[row * 64 + c4] = vv;
        }
        __syncthreads();

        // scores: S = Q K^T * scale
        float s[4][4];
#pragma unroll
        for (int i = 0; i < 4; ++i)
#pragma unroll
            for (int j = 0; j < 4; ++j) s[i][j] = 0.f;

#pragma unroll 8
        for (int d = 0; d < 64; ++d) {
            float4 a  = *(const float4*)&Qs[d * 64 + ((ty * 4) ^ SWZ(d))];
            float4 bq = *(const float4*)&KPs[d * 64 + ((tx * 4) ^ SWZ(d))];
            float av[4] = {a.x, a.y, a.z, a.w};
            float bv[4] = {bq.x, bq.y, bq.z, bq.w};
#pragma unroll
            for (int i = 0; i < 4; ++i)
#pragma unroll
                for (int j = 0; j < 4; ++j)
                    s[i][j] = fmaf(av[i], bv[j], s[i][j]);
        }

#pragma unroll
        for (int i = 0; i < 4; ++i)
#pragma unroll
            for (int j = 0; j < 4; ++j) s[i][j] *= 0.125f;  // 1/sqrt(64)

        if (kt == qt) {
#pragma unroll
            for (int i = 0; i < 4; ++i)
#pragma unroll
                for (int j = 0; j < 4; ++j)
                    if (tx * 4 + j > ty * 4 + i) s[i][j] = -1e30f;
        }

        // online softmax stats (row spread over 16 tx lanes = half warp)
        float alpha[4];
#pragma unroll
        for (int i = 0; i < 4; ++i) {
            float mx = fmaxf(fmaxf(s[i][0], s[i][1]), fmaxf(s[i][2], s[i][3]));
#pragma unroll
            for (int w = 1; w < 16; w <<= 1)
                mx = fmaxf(mx, __shfl_xor_sync(0xffffffffu, mx, w));
            float mnew = fmaxf(m_i[i], mx);
            alpha[i] = __expf(m_i[i] - mnew);
            m_i[i] = mnew;
            float rs = 0.f;
#pragma unroll
            for (int j = 0; j < 4; ++j) {
                s[i][j] = __expf(s[i][j] - mnew);
                rs += s[i][j];
            }
#pragma unroll
            for (int w = 1; w < 16; w <<= 1)
                rs += __shfl_xor_sync(0xffffffffu, rs, w);
            l_i[i] = l_i[i] * alpha[i] + rs;
#pragma unroll
            for (int j = 0; j < 4; ++j) acc[i][j] *= alpha[i];
        }

        __syncthreads();  // all threads done reading KPs as K tile

        // write P transposed into KPs: element (kcol c, qrow r) at [c][r^swz(c)]
#pragma unroll
        for (int i = 0; i < 4; ++i)
#pragma unroll
            for (int j = 0; j < 4; ++j) {
                int c = tx * 4 + j;
                KPs[c * 64 + ((ty * 4 + i) ^ SWZ(c))] = s[i][j];
            }
        __syncthreads();

        // O += P @ V
#pragma unroll 8
        for (int kk = 0; kk < 64; ++kk) {
            float4 a  = *(const float4*)&KPs[kk * 64 + ((ty * 4) ^ SWZ(kk))];
            float4 bv = *(const float4*)&Vs[kk * 64 + tx * 4];
            float av[4] = {a.x, a.y, a.z, a.w};
            float vv[4] = {bv.x, bv.y, bv.z, bv.w};
#pragma unroll
            for (int i = 0; i < 4; ++i)
#pragma unroll
                for (int j = 0; j < 4; ++j)
                    acc[i][j] = fmaf(av[i], vv[j], acc[i][j]);
        }
    }

    // epilogue: normalize, write [b, s, h*dk + d]
    float* obase = O + ((size_t)(b * SS) + qrow0) * D_MODEL + h * DK;
#pragma unroll
    for (int i = 0; i < 4; ++i) {
        float inv = 1.f / l_i[i];
        float4 o = make_float4(acc[i][0] * inv, acc[i][1] * inv,
                               acc[i][2] * inv, acc[i][3] * inv);
        *(float4*)(obase + (size_t)(ty * 4 + i) * D_MODEL + tx * 4) = o;
    }
}

// ---------------------------------------------------------------------------
extern "C" void kernel_launch(void* const* d_in, const int* in_sizes, int n_in,
                              void* d_out, int out_size)
{
    const float* wq  = (const float*)d_in[0];
    const float* wk  = (const float*)d_in[1];
    const float* wv  = (const float*)d_in[2];
    const float* wo  = (const float*)d_in[3];
    const float* x   = (const float*)d_in[4];
    const int*   pos = (const int*)d_in[5];
    float* out = (float*)d_out;

    float *dq, *dk, *dv, *datt;
    cudaGetSymbolAddress((void**)&dq,   g_q);
    cudaGetSymbolAddress((void**)&dk,   g_k);
    cudaGetSymbolAddress((void**)&dv,   g_v);
    cudaGetSymbolAddress((void**)&datt, g_att);

    dim3 gg(D_MODEL / 128, MM / 128);  // (8, 64)

    sgemm_nt_kernel<<<gg, 256>>>(x, wq, dq, MM, D_MODEL, D_MODEL);
    sgemm_nt_kernel<<<gg, 256>>>(x, wk, dk, MM, D_MODEL, D_MODEL);
    sgemm_nt_kernel<<<gg, 256>>>(x, wv, dv, MM, D_MODEL, D_MODEL);

    const int rope_total = MM * NUM_HEADS * HALF;  // 4,194,304
    rope_kernel<<<rope_total / 256, 256>>>(dq, dk, pos);

    attn_kernel<<<dim3(SS / 64, NUM_HEADS, BB), 256>>>(dq, dk, dv, datt);

    sgemm_nt_kernel<<<gg, 256>>>(datt, wo, out, MM, D_MODEL, D_MODEL);
}

// round 4
// speedup vs baseline: 1.4789x; 1.4789x over previous
#include <cuda_runtime.h>
#include <cuda_bf16.h>
#include <math.h>
#include <stdint.h>

#define D_MODEL 1024
#define NUM_HEADS 16
#define DK 64
#define HALF 32
#define BB 4
#define SS 2048
#define MM (BB * SS)           // 8192 tokens
#define LOG2_THETA 13.287712379549449f   // log2(10000)

// ---------------- scratch (device globals: no allocation allowed) ----------
__device__ float g_q[(size_t)MM * D_MODEL];
__device__ float g_k[(size_t)MM * D_MODEL];
__device__ float g_v[(size_t)MM * D_MODEL];
__device__ float g_att[(size_t)MM * D_MODEL];

__device__ __nv_bfloat16 g_xh[(size_t)MM * D_MODEL];
__device__ __nv_bfloat16 g_xl[(size_t)MM * D_MODEL];
__device__ __nv_bfloat16 g_ah[(size_t)MM * D_MODEL];
__device__ __nv_bfloat16 g_al[(size_t)MM * D_MODEL];
__device__ __nv_bfloat16 g_wh[4][(size_t)D_MODEL * D_MODEL];
__device__ __nv_bfloat16 g_wl[4][(size_t)D_MODEL * D_MODEL];

// ---------------------------------------------------------------------------
// fp32 -> (bf16 hi, bf16 lo) split.  lo = bf16(x - float(hi)).
// ---------------------------------------------------------------------------
__global__ void __launch_bounds__(256) split_bf16_kernel(
    const float* __restrict__ src, __nv_bfloat16* __restrict__ hi,
    __nv_bfloat16* __restrict__ lo, int n4)
{
    int i = blockIdx.x * blockDim.x + threadIdx.x;
    if (i >= n4) return;
    float4 v = ((const float4*)src)[i];
    __nv_bfloat16 h0 = __float2bfloat16_rn(v.x);
    __nv_bfloat16 h1 = __float2bfloat16_rn(v.y);
    __nv_bfloat16 h2 = __float2bfloat16_rn(v.z);
    __nv_bfloat16 h3 = __float2bfloat16_rn(v.w);
    __nv_bfloat16 l0 = __float2bfloat16_rn(v.x - __bfloat162float(h0));
    __nv_bfloat16 l1 = __float2bfloat16_rn(v.y - __bfloat162float(h1));
    __nv_bfloat16 l2 = __float2bfloat16_rn(v.z - __bfloat162float(h2));
    __nv_bfloat16 l3 = __float2bfloat16_rn(v.w - __bfloat162float(h3));
    ((__nv_bfloat162*)hi)[i * 2 + 0] = __nv_bfloat162(h0, h1);
    ((__nv_bfloat162*)hi)[i * 2 + 1] = __nv_bfloat162(h2, h3);
    ((__nv_bfloat162*)lo)[i * 2 + 0] = __nv_bfloat162(l0, l1);
    ((__nv_bfloat162*)lo)[i * 2 + 1] = __nv_bfloat162(l2, l3);
}

// ---------------------------------------------------------------------------
// bf16x3 tensor-core GEMM (NT): C[M,N] = (Ah+Al)[M,K] * (Bh+Bl)[N,K]^T
// 128x128 tile, BK=16, 256 threads (8 warps, 2x4), warp tile 64x32.
// Smem holds bf16x2 words in m16n8k16 fragment order -> lane-linear LDS.32.
// 3 MMAs per (i,j): hi*hi + hi*lo + lo*hi, fp32 accumulate.
// ---------------------------------------------------------------------------
__device__ __forceinline__ uint32_t smem_u32(const void* p) {
    return (uint32_t)__cvta_generic_to_shared(p);
}

#define CP_ASYNC16(dst, src) \
    asm volatile("cp.async.cg.shared.global [%0], [%1], 16;\n" :: "r"(dst), "l"(src))
#define CP_COMMIT() asm volatile("cp.async.commit_group;\n" ::: "memory")
#define CP_WAIT1()  asm volatile("cp.async.wait_group 1;\n" ::: "memory")
#define CP_WAIT0()  asm volatile("cp.async.wait_group 0;\n" ::: "memory")

__device__ __forceinline__ void mma_bf16(float c[4], const uint32_t a[4],
                                         const uint32_t b[2]) {
    asm volatile(
        "mma.sync.aligned.m16n8k16.row.col.f32.bf16.bf16.f32 "
        "{%0,%1,%2,%3}, {%4,%5,%6,%7}, {%8,%9}, {%0,%1,%2,%3};\n"
        : "+f"(c[0]), "+f"(c[1]), "+f"(c[2]), "+f"(c[3])
        : "r"(a[0]), "r"(a[1]), "r"(a[2]), "r"(a[3]), "r"(b[0]), "r"(b[1]));
}

// One BK=16 slab of Ah/Al/Bh/Bl into fragment-ordered smem.
// Each thread: row m = tid>>1 (0..127), half q = tid&1 (k 0..7 / 8..15),
// one 16B chunk (8 bf16) per array.
__device__ __forceinline__ void load_stage(
    const __nv_bfloat16* __restrict__ gAh, const __nv_bfloat16* __restrict__ gAl,
    const __nv_bfloat16* __restrict__ gBh, const __nv_bfloat16* __restrict__ gBl,
    int Kdim, int k0,
    uint32_t* sAh, uint32_t* sAl, uint32_t* sBh, uint32_t* sBl, int tid)
{
    const int m = tid >> 1;
    const int q = tid & 1;
    const size_t src = (size_t)m * Kdim + k0 + q * 8;
    // A word base: tile m>>4, reg = ((m>>3)&1) + 2q, lanes (m&7)*4 ..+3
    const int aw = ((((m >> 4) * 4 + ((m >> 3) & 1) + 2 * q)) << 5) + (m & 7) * 4;
    // B word base: tile m>>3, reg = q, lanes (m&7)*4 ..+3
    const int bw = ((((m >> 3) * 2 + q)) << 5) + (m & 7) * 4;
    CP_ASYNC16(smem_u32(sAh + aw), gAh + src);
    CP_ASYNC16(smem_u32(sAl + aw), gAl + src);
    CP_ASYNC16(smem_u32(sBh + bw), gBh + src);
    CP_ASYNC16(smem_u32(sBl + bw), gBl + src);
}

__global__ void __launch_bounds__(256) gemm_bf16x3_nt(
    const __nv_bfloat16* __restrict__ Ah, const __nv_bfloat16* __restrict__ Al,
    const __nv_bfloat16* __restrict__ Bh, const __nv_bfloat16* __restrict__ Bl,
    float* __restrict__ C, int Mdim, int Ndim, int Kdim)
{
    __shared__ uint32_t sAh[2][1024];   // 4KB each stage/array
    __shared__ uint32_t sAl[2][1024];
    __shared__ uint32_t sBh[2][1024];
    __shared__ uint32_t sBl[2][1024];

    const int tid  = threadIdx.x;
    const int lane = tid & 31;
    const int warp = tid >> 5;
    const int wy   = warp >> 2;     // 0..1  -> 64 rows
    const int wx   = warp & 3;      // 0..3  -> 32 cols
    const int row0 = blockIdx.y * 128;
    const int col0 = blockIdx.x * 128;

    const __nv_bfloat16* gAh = Ah + (size_t)row0 * Kdim;
    const __nv_bfloat16* gAl = Al + (size_t)row0 * Kdim;
    const __nv_bfloat16* gBh = Bh + (size_t)col0 * Kdim;
    const __nv_bfloat16* gBl = Bl + (size_t)col0 * Kdim;

    float c[4][4][4];
#pragma unroll
    for (int i = 0; i < 4; ++i)
#pragma unroll
        for (int j = 0; j < 4; ++j)
#pragma unroll
            for (int r = 0; r < 4; ++r) c[i][j][r] = 0.f;

    load_stage(gAh, gAl, gBh, gBl, Kdim, 0, sAh[0], sAl[0], sBh[0], sBl[0], tid);
    CP_COMMIT();

    const int NT = Kdim / 16;
    for (int t = 0; t < NT; ++t) {
        if (t + 1 < NT) {
            int s = (t + 1) & 1;
            load_stage(gAh, gAl, gBh, gBl, Kdim, (t + 1) * 16,
                       sAh[s], sAl[s], sBh[s], sBl[s], tid);
            CP_COMMIT();
            CP_WAIT1();
        } else {
            CP_WAIT0();
        }
        __syncthreads();

        const uint32_t* pAh = sAh[t & 1];
        const uint32_t* pAl = sAl[t & 1];
        const uint32_t* pBh = sBh[t & 1];
        const uint32_t* pBl = sBl[t & 1];

        uint32_t ah[4][4], al[4][4], bh[4][2], bl[4][2];
#pragma unroll
        for (int i = 0; i < 4; ++i) {
            const int base = (((wy * 4 + i) * 4) << 5) + lane;
#pragma unroll
            for (int r = 0; r < 4; ++r) {
                ah[i][r] = pAh[base + (r << 5)];
                al[i][r] = pAl[base + (r << 5)];
            }
        }
#pragma unroll
        for (int j = 0; j < 4; ++j) {
            const int base = (((wx * 4 + j) * 2) << 5) + lane;
#pragma unroll
            for (int r = 0; r < 2; ++r) {
                bh[j][r] = pBh[base + (r << 5)];
                bl[j][r] = pBl[base + (r << 5)];
            }
        }

#pragma unroll
        for (int i = 0; i < 4; ++i)
#pragma unroll
            for (int j = 0; j < 4; ++j) {
                mma_bf16(c[i][j], ah[i], bh[j]);
                mma_bf16(c[i][j], ah[i], bl[j]);
                mma_bf16(c[i][j], al[i], bh[j]);
            }
        __syncthreads();
    }

    // epilogue: m16n8 C layout
    const int r  = lane >> 2;
    const int cc = (lane & 3) * 2;
#pragma unroll
    for (int i = 0; i < 4; ++i)
#pragma unroll
        for (int j = 0; j < 4; ++j) {
            float* cp = C + (size_t)(row0 + wy * 64 + i * 16 + r) * Ndim
                          + col0 + wx * 32 + j * 8 + cc;
            *(float2*)cp = make_float2(c[i][j][0], c[i][j][1]);
            *(float2*)(cp + 8 * (size_t)Ndim) = make_float2(c[i][j][2], c[i][j][3]);
        }
}

// ---------------------------------------------------------------------------
// RoPE: in-place on q and k. One thread per (token m, head h, freq i).
// ---------------------------------------------------------------------------
__global__ void __launch_bounds__(256) rope_kernel(
    float* __restrict__ q, float* __restrict__ k, const int* __restrict__ pos)
{
    const int idx = blockIdx.x * blockDim.x + threadIdx.x;  // < MM*H*HALF
    const int i = idx & (HALF - 1);
    const int h = (idx >> 5) & (NUM_HEADS - 1);
    const int m = idx >> 9;
    const int s = m & (SS - 1);

    const float p = (float)pos[s];
    const float inv_freq = exp2f(-(float)i * (LOG2_THETA / (float)HALF));
    float sn, cs;
    sincosf(p * inv_freq, &sn, &cs);

    const size_t base = (size_t)m * D_MODEL + h * DK + 2 * i;

    float2 qv = *(float2*)(q + base);
    *(float2*)(q + base) = make_float2(qv.x * cs - qv.y * sn, qv.x * sn + qv.y * cs);
    float2 kv = *(float2*)(k + base);
    *(float2*)(k + base) = make_float2(kv.x * cs - kv.y * sn, kv.x * sn + kv.y * cs);
}

// ---------------------------------------------------------------------------
// Flash attention (causal), fp32. Block = one (b, h, 64-row q tile).
// 256 threads as 16x16; each thread owns a 4x4 micro-tile.
// ---------------------------------------------------------------------------
#define SWZ(x) ((((x) >> 2) & 7) << 2)

__global__ void __launch_bounds__(256) attn_kernel(
    const float* __restrict__ Q, const float* __restrict__ K,
    const float* __restrict__ V, float* __restrict__ O)
{
    __shared__ float Qs[64 * 64];   // [d][row^swz(d)]
    __shared__ float KPs[64 * 64];  // K tile [d][col^swz(d)], then P tile
    __shared__ float Vs[64 * 64];   // [krow][d]

    const int qt = blockIdx.x;
    const int h  = blockIdx.y;
    const int b  = blockIdx.z;
    const int tid = threadIdx.x;
    const int tx = tid & 15;
    const int ty = tid >> 4;

    const float* qbase = Q + ((size_t)(b * SS) + qt * 64) * D_MODEL + h * DK;

#pragma unroll
    for (int it = 0; it < 4; ++it) {
        int f4  = tid + it * 256;
        int row = f4 >> 4;
        int c4  = (f4 & 15) * 4;
        float4 vq = *(const float4*)(qbase + (size_t)row * D_MODEL + c4);
        Qs[(c4 + 0) * 64 + (row ^ SWZ(c4 + 0))] = vq.x;
        Qs[(c4 + 1) * 64 + (row ^ SWZ(c4 + 1))] = vq.y;
        Qs[(c4 + 2) * 64 + (row ^ SWZ(c4 + 2))] = vq.z;
        Qs[(c4 + 3) * 64 + (row ^ SWZ(c4 + 3))] = vq.w;
    }

    float m_i[4], l_i[4], acc[4][4];
#pragma unroll
    for (int i = 0; i < 4; ++i) {
        m_i[i] = -1e30f; l_i[i] = 0.f;
#pragma unroll
        for (int j = 0; j < 4; ++j) acc[i][j] = 0.f;
    }

    const int qrow0 = qt * 64;

    for (int kt = 0; kt <= qt; ++kt) {
        __syncthreads();

        const float* kbase = K + ((size_t)(b * SS) + kt * 64) * D_MODEL + h * DK;
        const float* vbase = V + ((size_t)(b * SS) + kt * 64) * D_MODEL + h * DK;
#pragma unroll
        for (int it = 0; it < 4; ++it) {
            int f4  = tid + it * 256;
            int row = f4 >> 4;
            int c4  = (f4 & 15) * 4;
            float4 kv = *(const float4*)(kbase + (size_t)row * D_MODEL + c4);
            KPs[(c4 + 0) * 64 + (row ^ SWZ(c4 + 0))] = kv.x;
            KPs[(c4 + 1) * 64 + (row ^ SWZ(c4 + 1))] = kv.y;
            KPs[(c4 + 2) * 64 + (row ^ SWZ(c4 + 2))] = kv.z;
            KPs[(c4 + 3) * 64 + (row ^ SWZ(c4 + 3))] = kv.w;
            float4 vv = *(const float4*)(vbase + (size_t)row * D_MODEL + c4);
            *(float4*)&Vs[row * 64 + c4] = vv;
        }
        __syncthreads();

        float s[4][4];
#pragma unroll
        for (int i = 0; i < 4; ++i)
#pragma unroll
            for (int j = 0; j < 4; ++j) s[i][j] = 0.f;

#pragma unroll 8
        for (int d = 0; d < 64; ++d) {
            float4 a  = *(const float4*)&Qs[d * 64 + ((ty * 4) ^ SWZ(d))];
            float4 bq = *(const float4*)&KPs[d * 64 + ((tx * 4) ^ SWZ(d))];
            float av[4] = {a.x, a.y, a.z, a.w};
            float bv[4] = {bq.x, bq.y, bq.z, bq.w};
#pragma unroll
            for (int i = 0; i < 4; ++i)
#pragma unroll
                for (int j = 0; j < 4; ++j)
                    s[i][j] = fmaf(av[i], bv[j], s[i][j]);
        }

#pragma unroll
        for (int i = 0; i < 4; ++i)
#pragma unroll
            for (int j = 0; j < 4; ++j) s[i][j] *= 0.125f;

        if (kt == qt) {
#pragma unroll
            for (int i = 0; i < 4; ++i)
#pragma unroll
                for (int j = 0; j < 4; ++j)
                    if (tx * 4 + j > ty * 4 + i) s[i][j] = -1e30f;
        }

        float alpha[4];
#pragma unroll
        for (int i = 0; i < 4; ++i) {
            float mx = fmaxf(fmaxf(s[i][0], s[i][1]), fmaxf(s[i][2], s[i][3]));
#pragma unroll
            for (int w = 1; w < 16; w <<= 1)
                mx = fmaxf(mx, __shfl_xor_sync(0xffffffffu, mx, w));
            float mnew = fmaxf(m_i[i], mx);
            alpha[i] = __expf(m_i[i] - mnew);
            m_i[i] = mnew;
            float rs = 0.f;
#pragma unroll
            for (int j = 0; j < 4; ++j) {
                s[i][j] = __expf(s[i][j] - mnew);
                rs += s[i][j];
            }
#pragma unroll
            for (int w = 1; w < 16; w <<= 1)
                rs += __shfl_xor_sync(0xffffffffu, rs, w);
            l_i[i] = l_i[i] * alpha[i] + rs;
#pragma unroll
            for (int j = 0; j < 4; ++j) acc[i][j] *= alpha[i];
        }

        __syncthreads();

#pragma unroll
        for (int i = 0; i < 4; ++i)
#pragma unroll
            for (int j = 0; j < 4; ++j) {
                int cix = tx * 4 + j;
                KPs[cix * 64 + ((ty * 4 + i) ^ SWZ(cix))] = s[i][j];
            }
        __syncthreads();

#pragma unroll 8
        for (int kk = 0; kk < 64; ++kk) {
            float4 a  = *(const float4*)&KPs[kk * 64 + ((ty * 4) ^ SWZ(kk))];
            float4 bv = *(const float4*)&Vs[kk * 64 + tx * 4];
            float av[4] = {a.x, a.y, a.z, a.w};
            float vv[4] = {bv.x, bv.y, bv.z, bv.w};
#pragma unroll
            for (int i = 0; i < 4; ++i)
#pragma unroll
                for (int j = 0; j < 4; ++j)
                    acc[i][j] = fmaf(av[i], vv[j], acc[i][j]);
        }
    }

    float* obase = O + ((size_t)(b * SS) + qrow0) * D_MODEL + h * DK;
#pragma unroll
    for (int i = 0; i < 4; ++i) {
        float inv = 1.f / l_i[i];
        float4 o = make_float4(acc[i][0] * inv, acc[i][1] * inv,
                               acc[i][2] * inv, acc[i][3] * inv);
        *(float4*)(obase + (size_t)(ty * 4 + i) * D_MODEL + tx * 4) = o;
    }
}

// ---------------------------------------------------------------------------
extern "C" void kernel_launch(void* const* d_in, const int* in_sizes, int n_in,
                              void* d_out, int out_size)
{
    const float* wq  = (const float*)d_in[0];
    const float* wk  = (const float*)d_in[1];
    const float* wv  = (const float*)d_in[2];
    const float* wo  = (const float*)d_in[3];
    const float* x   = (const float*)d_in[4];
    const int*   pos = (const int*)d_in[5];
    float* out = (float*)d_out;

    float *dq, *dk, *dv, *datt;
    cudaGetSymbolAddress((void**)&dq,   g_q);
    cudaGetSymbolAddress((void**)&dk,   g_k);
    cudaGetSymbolAddress((void**)&dv,   g_v);
    cudaGetSymbolAddress((void**)&datt, g_att);
    __nv_bfloat16 *xh, *xl, *ath, *atl, *wh, *wl;
    cudaGetSymbolAddress((void**)&xh,  g_xh);
    cudaGetSymbolAddress((void**)&xl,  g_xl);
    cudaGetSymbolAddress((void**)&ath, g_ah);
    cudaGetSymbolAddress((void**)&atl, g_al);
    cudaGetSymbolAddress((void**)&wh,  g_wh);
    cudaGetSymbolAddress((void**)&wl,  g_wl);

    const size_t WSZ = (size_t)D_MODEL * D_MODEL;
    const int n4x = (int)((size_t)MM * D_MODEL / 4);
    const int n4w = (int)(WSZ / 4);

    // split fp32 -> bf16 hi/lo
    split_bf16_kernel<<<(n4x + 255) / 256, 256>>>(x, xh, xl, n4x);
    split_bf16_kernel<<<(n4w + 255) / 256, 256>>>(wq, wh + 0 * WSZ, wl + 0 * WSZ, n4w);
    split_bf16_kernel<<<(n4w + 255) / 256, 256>>>(wk, wh + 1 * WSZ, wl + 1 * WSZ, n4w);
    split_bf16_kernel<<<(n4w + 255) / 256, 256>>>(wv, wh + 2 * WSZ, wl + 2 * WSZ, n4w);
    split_bf16_kernel<<<(n4w + 255) / 256, 256>>>(wo, wh + 3 * WSZ, wl + 3 * WSZ, n4w);

    dim3 gg(D_MODEL / 128, MM / 128);  // (8, 64)

    gemm_bf16x3_nt<<<gg, 256>>>(xh, xl, wh + 0 * WSZ, wl + 0 * WSZ, dq, MM, D_MODEL, D_MODEL);
    gemm_bf16x3_nt<<<gg, 256>>>(xh, xl, wh + 1 * WSZ, wl + 1 * WSZ, dk, MM, D_MODEL, D_MODEL);
    gemm_bf16x3_nt<<<gg, 256>>>(xh, xl, wh + 2 * WSZ, wl + 2 * WSZ, dv, MM, D_MODEL, D_MODEL);

    const int rope_total = MM * NUM_HEADS * HALF;  // 4,194,304
    rope_kernel<<<rope_total / 256, 256>>>(dq, dk, pos);

    attn_kernel<<<dim3(SS / 64, NUM_HEADS, BB), 256>>>(dq, dk, dv, datt);

    split_bf16_kernel<<<(n4x + 255) / 256, 256>>>(datt, ath, atl, n4x);
    gemm_bf16x3_nt<<<gg, 256>>>(ath, atl, wh + 3 * WSZ, wl + 3 * WSZ, out, MM, D_MODEL, D_MODEL);
}

// round 5
// speedup vs baseline: 2.2829x; 1.5437x over previous
#include <cuda_runtime.h>
#include <cuda_bf16.h>
#include <math.h>
#include <stdint.h>

#define D_MODEL 1024
#define NUM_HEADS 16
#define DK 64
#define HALF 32
#define BB 4
#define SS 2048
#define MM (BB * SS)           // 8192 tokens
#define LOG2_THETA 13.287712379549449f   // log2(10000)

// ---------------- scratch (device globals: no allocation allowed) ----------
__device__ float g_q[(size_t)MM * D_MODEL];
__device__ float g_k[(size_t)MM * D_MODEL];
__device__ float g_v[(size_t)MM * D_MODEL];
__device__ float g_att[(size_t)MM * D_MODEL];

__device__ __nv_bfloat16 g_xh[(size_t)MM * D_MODEL];
__device__ __nv_bfloat16 g_xl[(size_t)MM * D_MODEL];
__device__ __nv_bfloat16 g_ah[(size_t)MM * D_MODEL];
__device__ __nv_bfloat16 g_al[(size_t)MM * D_MODEL];
__device__ __nv_bfloat16 g_wh[4][(size_t)D_MODEL * D_MODEL];
__device__ __nv_bfloat16 g_wl[4][(size_t)D_MODEL * D_MODEL];

__device__ __nv_bfloat16 g_qh[(size_t)MM * D_MODEL];
__device__ __nv_bfloat16 g_ql[(size_t)MM * D_MODEL];
__device__ __nv_bfloat16 g_kh[(size_t)MM * D_MODEL];
__device__ __nv_bfloat16 g_kl[(size_t)MM * D_MODEL];
__device__ __nv_bfloat16 g_vth[(size_t)MM * D_MODEL];  // [(b*16+h)*64+d][S]
__device__ __nv_bfloat16 g_vtl[(size_t)MM * D_MODEL];

// ---------------------------------------------------------------------------
__device__ __forceinline__ uint32_t smem_u32(const void* p) {
    return (uint32_t)__cvta_generic_to_shared(p);
}
#define CP_ASYNC16(dst, src) \
    asm volatile("cp.async.cg.shared.global [%0], [%1], 16;\n" :: "r"(dst), "l"(src))
#define CP_COMMIT() asm volatile("cp.async.commit_group;\n" ::: "memory")
#define CP_WAIT1()  asm volatile("cp.async.wait_group 1;\n" ::: "memory")
#define CP_WAIT0()  asm volatile("cp.async.wait_group 0;\n" ::: "memory")

__device__ __forceinline__ void mma_bf16(float c[4], const uint32_t a[4],
                                         const uint32_t b[2]) {
    asm volatile(
        "mma.sync.aligned.m16n8k16.row.col.f32.bf16.bf16.f32 "
        "{%0,%1,%2,%3}, {%4,%5,%6,%7}, {%8,%9}, {%0,%1,%2,%3};\n"
        : "+f"(c[0]), "+f"(c[1]), "+f"(c[2]), "+f"(c[3])
        : "r"(a[0]), "r"(a[1]), "r"(a[2]), "r"(a[3]), "r"(b[0]), "r"(b[1]));
}

__device__ __forceinline__ void split2(float x, float y, uint32_t& hi, uint32_t& lo) {
    __nv_bfloat162 h = __floats2bfloat162_rn(x, y);
    float hx = __bfloat162float(h.x), hy = __bfloat162float(h.y);
    __nv_bfloat162 l = __floats2bfloat162_rn(x - hx, y - hy);
    hi = *(uint32_t*)&h;
    lo = *(uint32_t*)&l;
}

// ---------------------------------------------------------------------------
// fp32 -> (bf16 hi, bf16 lo) split.
// ---------------------------------------------------------------------------
__global__ void __launch_bounds__(256) split_bf16_kernel(
    const float* __restrict__ src, __nv_bfloat16* __restrict__ hi,
    __nv_bfloat16* __restrict__ lo, int n4)
{
    int i = blockIdx.x * blockDim.x + threadIdx.x;
    if (i >= n4) return;
    float4 v = ((const float4*)src)[i];
    uint32_t h0, l0, h1, l1;
    split2(v.x, v.y, h0, l0);
    split2(v.z, v.w, h1, l1);
    ((uint32_t*)hi)[i * 2 + 0] = h0;
    ((uint32_t*)hi)[i * 2 + 1] = h1;
    ((uint32_t*)lo)[i * 2 + 0] = l0;
    ((uint32_t*)lo)[i * 2 + 1] = l1;
}

// ---------------------------------------------------------------------------
// bf16x3 tensor-core GEMM (NT) — unchanged from round 4 (validated).
// ---------------------------------------------------------------------------
__device__ __forceinline__ void load_stage(
    const __nv_bfloat16* __restrict__ gAh, const __nv_bfloat16* __restrict__ gAl,
    const __nv_bfloat16* __restrict__ gBh, const __nv_bfloat16* __restrict__ gBl,
    int Kdim, int k0,
    uint32_t* sAh, uint32_t* sAl, uint32_t* sBh, uint32_t* sBl, int tid)
{
    const int m = tid >> 1;
    const int q = tid & 1;
    const size_t src = (size_t)m * Kdim + k0 + q * 8;
    const int aw = ((((m >> 4) * 4 + ((m >> 3) & 1) + 2 * q)) << 5) + (m & 7) * 4;
    const int bw = ((((m >> 3) * 2 + q)) << 5) + (m & 7) * 4;
    CP_ASYNC16(smem_u32(sAh + aw), gAh + src);
    CP_ASYNC16(smem_u32(sAl + aw), gAl + src);
    CP_ASYNC16(smem_u32(sBh + bw), gBh + src);
    CP_ASYNC16(smem_u32(sBl + bw), gBl + src);
}

__global__ void __launch_bounds__(256) gemm_bf16x3_nt(
    const __nv_bfloat16* __restrict__ Ah, const __nv_bfloat16* __restrict__ Al,
    const __nv_bfloat16* __restrict__ Bh, const __nv_bfloat16* __restrict__ Bl,
    float* __restrict__ C, int Mdim, int Ndim, int Kdim)
{
    __shared__ uint32_t sAh[2][1024];
    __shared__ uint32_t sAl[2][1024];
    __shared__ uint32_t sBh[2][1024];
    __shared__ uint32_t sBl[2][1024];

    const int tid  = threadIdx.x;
    const int lane = tid & 31;
    const int warp = tid >> 5;
    const int wy   = warp >> 2;
    const int wx   = warp & 3;
    const int row0 = blockIdx.y * 128;
    const int col0 = blockIdx.x * 128;

    const __nv_bfloat16* gAh = Ah + (size_t)row0 * Kdim;
    const __nv_bfloat16* gAl = Al + (size_t)row0 * Kdim;
    const __nv_bfloat16* gBh = Bh + (size_t)col0 * Kdim;
    const __nv_bfloat16* gBl = Bl + (size_t)col0 * Kdim;

    float c[4][4][4];
#pragma unroll
    for (int i = 0; i < 4; ++i)
#pragma unroll
        for (int j = 0; j < 4; ++j)
#pragma unroll
            for (int r = 0; r < 4; ++r) c[i][j][r] = 0.f;

    load_stage(gAh, gAl, gBh, gBl, Kdim, 0, sAh[0], sAl[0], sBh[0], sBl[0], tid);
    CP_COMMIT();

    const int NT = Kdim / 16;
    for (int t = 0; t < NT; ++t) {
        if (t + 1 < NT) {
            int s = (t + 1) & 1;
            load_stage(gAh, gAl, gBh, gBl, Kdim, (t + 1) * 16,
                       sAh[s], sAl[s], sBh[s], sBl[s], tid);
            CP_COMMIT();
            CP_WAIT1();
        } else {
            CP_WAIT0();
        }
        __syncthreads();

        const uint32_t* pAh = sAh[t & 1];
        const uint32_t* pAl = sAl[t & 1];
        const uint32_t* pBh = sBh[t & 1];
        const uint32_t* pBl = sBl[t & 1];

        uint32_t ah[4][4], al[4][4], bh[4][2], bl[4][2];
#pragma unroll
        for (int i = 0; i < 4; ++i) {
            const int base = (((wy * 4 + i) * 4) << 5) + lane;
#pragma unroll
            for (int r = 0; r < 4; ++r) {
                ah[i][r] = pAh[base + (r << 5)];
                al[i][r] = pAl[base + (r << 5)];
            }
        }
#pragma unroll
        for (int j = 0; j < 4; ++j) {
            const int base = (((wx * 4 + j) * 2) << 5) + lane;
#pragma unroll
            for (int r = 0; r < 2; ++r) {
                bh[j][r] = pBh[base + (r << 5)];
                bl[j][r] = pBl[base + (r << 5)];
            }
        }

#pragma unroll
        for (int i = 0; i < 4; ++i)
#pragma unroll
            for (int j = 0; j < 4; ++j) {
                mma_bf16(c[i][j], ah[i], bh[j]);
                mma_bf16(c[i][j], ah[i], bl[j]);
                mma_bf16(c[i][j], al[i], bh[j]);
            }
        __syncthreads();
    }

    const int r  = lane >> 2;
    const int cc = (lane & 3) * 2;
#pragma unroll
    for (int i = 0; i < 4; ++i)
#pragma unroll
        for (int j = 0; j < 4; ++j) {
            float* cp = C + (size_t)(row0 + wy * 64 + i * 16 + r) * Ndim
                          + col0 + wx * 32 + j * 8 + cc;
            *(float2*)cp = make_float2(c[i][j][0], c[i][j][1]);
            *(float2*)(cp + 8 * (size_t)Ndim) = make_float2(c[i][j][2], c[i][j][3]);
        }
}

// ---------------------------------------------------------------------------
// RoPE + split: reads fp32 q,k; writes rotated bf16 hi/lo.
// ---------------------------------------------------------------------------
__global__ void __launch_bounds__(256) rope_split_kernel(
    const float* __restrict__ q, const float* __restrict__ k,
    const int* __restrict__ pos,
    __nv_bfloat16* __restrict__ qh, __nv_bfloat16* __restrict__ ql,
    __nv_bfloat16* __restrict__ kh, __nv_bfloat16* __restrict__ kl)
{
    const int idx = blockIdx.x * blockDim.x + threadIdx.x;  // < MM*H*HALF
    const int i = idx & (HALF - 1);
    const int h = (idx >> 5) & (NUM_HEADS - 1);
    const int m = idx >> 9;
    const int s = m & (SS - 1);

    const float p = (float)pos[s];
    const float inv_freq = exp2f(-(float)i * (LOG2_THETA / (float)HALF));
    float sn, cs;
    sincosf(p * inv_freq, &sn, &cs);

    const size_t base = (size_t)m * D_MODEL + h * DK + 2 * i;

    float2 qv = *(const float2*)(q + base);
    float2 kv = *(const float2*)(k + base);
    float qe = qv.x * cs - qv.y * sn, qo = qv.x * sn + qv.y * cs;
    float ke = kv.x * cs - kv.y * sn, ko = kv.x * sn + kv.y * cs;

    uint32_t hh, ll;
    split2(qe, qo, hh, ll);
    *(uint32_t*)(qh + base) = hh; *(uint32_t*)(ql + base) = ll;
    split2(ke, ko, hh, ll);
    *(uint32_t*)(kh + base) = hh; *(uint32_t*)(kl + base) = ll;
}

// ---------------------------------------------------------------------------
// V transpose + split: g_v fp32 [b*S+t][1024] -> vth/vtl [(b*16+h)*64+d][S]
// One block per (64t x 64d) tile of one (b,h).
// ---------------------------------------------------------------------------
__global__ void __launch_bounds__(256) vtrans_split_kernel(
    const float* __restrict__ v,
    __nv_bfloat16* __restrict__ vth, __nv_bfloat16* __restrict__ vtl)
{
    __shared__ float tile[64][65];
    const int tb = blockIdx.x;            // t-chunk (0..31)
    const int bh = blockIdx.y;            // b*16+h  (0..63)
    const int b  = bh >> 4, h = bh & 15;
    const int tid = threadIdx.x;

#pragma unroll
    for (int i = 0; i < 4; ++i) {
        int e = tid + i * 256;            // 0..1023
        int t = e >> 4;
        int d4 = (e & 15) * 4;
        float4 vv = *(const float4*)(v + (size_t)(b * SS + tb * 64 + t) * D_MODEL
                                       + h * DK + d4);
        tile[d4 + 0][t] = vv.x;
        tile[d4 + 1][t] = vv.y;
        tile[d4 + 2][t] = vv.z;
        tile[d4 + 3][t] = vv.w;
    }
    __syncthreads();

#pragma unroll
    for (int i = 0; i < 8; ++i) {
        int e = tid + i * 256;            // 0..2047
        int d = e >> 5;
        int t2 = (e & 31) * 2;
        uint32_t hh, ll;
        split2(tile[d][t2], tile[d][t2 + 1], hh, ll);
        size_t dst = ((size_t)(bh * 64 + d)) * SS + tb * 64 + t2;
        *(uint32_t*)(vth + dst) = hh;
        *(uint32_t*)(vtl + dst) = ll;
    }
}

// ---------------------------------------------------------------------------
// Tensor-core flash attention (causal), bf16x3.
// Block: 128 q-rows of one (b,h). 8 warps x 16 rows. K/V tiles of 64 tokens.
// Dynamic smem 64KB: 2 stages x (Kh|Kl|Vh|Vl 8KB each); Q(32KB) overlays stage1.
// Fragment-order smem -> lane-linear LDS. P passes QK->PV in registers.
// ---------------------------------------------------------------------------
__global__ void __launch_bounds__(256, 1) attn_tc_kernel(
    const __nv_bfloat16* __restrict__ Qh, const __nv_bfloat16* __restrict__ Ql,
    const __nv_bfloat16* __restrict__ Kh, const __nv_bfloat16* __restrict__ Kl,
    const __nv_bfloat16* __restrict__ Vth, const __nv_bfloat16* __restrict__ Vtl,
    float* __restrict__ O)
{
    extern __shared__ uint32_t dsm[];   // 16384 u32 = 64KB

    const int qi  = blockIdx.x;         // 0..15
    const int h   = blockIdx.y;
    const int b   = blockIdx.z;
    const int tid = threadIdx.x;
    const int lane = tid & 31;
    const int w    = tid >> 5;

    const int tok0 = b * SS + qi * 128;       // global token base of q-block
    const int hoff = h * DK;
    const size_t vrow0 = (size_t)((b * 16 + h) * 64) * SS;
    const int kt_last = qi * 2 + 1;

    // ---- prologue: Q into stage1 region (words 8192..16383), K0/V0 stage0 ----
#pragma unroll
    for (int i = 0; i < 8; ++i) {
        int c   = tid + i * 256;              // 0..2047
        int arr = c >> 10;                    // 0 hi, 1 lo
        int cc  = c & 1023;
        int m = cc >> 3, kq = cc & 7;
        int wd = ((((m >> 4) * 4 + (kq >> 1)) * 4 + ((m >> 3) & 1) + 2 * (kq & 1)) << 5)
                 + (m & 7) * 4;
        const __nv_bfloat16* src = (arr ? Ql : Qh)
            + (size_t)(tok0 + m) * D_MODEL + hoff + kq * 8;
        CP_ASYNC16(smem_u32(dsm + 8192 + arr * 4096 + wd), src);
    }
    // K/V tile 0 into stage 0
    {
        const int kt = 0, sb = 0;
#pragma unroll
        for (int i = 0; i < 8; ++i) {
            int c = tid + i * 256;
            if (c < 1024) {
                int arr = c >> 9, cc = c & 511;
                int t = cc >> 3, kq = cc & 7;
                int wd = ((((t >> 3) * 4 + (kq >> 1)) * 2 + (kq & 1)) << 5) + (t & 7) * 4;
                const __nv_bfloat16* src = (arr ? Kl : Kh)
                    + (size_t)(b * SS + kt * 64 + t) * D_MODEL + hoff + kq * 8;
                CP_ASYNC16(smem_u32(dsm + sb + arr * 2048 + wd), src);
            } else {
                int c2 = c - 1024;
                int arr = c2 >> 9, cc = c2 & 511;
                int d = cc >> 3, tq = cc & 7;
                int wd = ((((d >> 3) * 4 + (tq >> 1)) * 2 + (tq & 1)) << 5) + (d & 7) * 4;
                const __nv_bfloat16* src = (arr ? Vtl : Vth)
                    + vrow0 + (size_t)d * SS + kt * 64 + tq * 8;
                CP_ASYNC16(smem_u32(dsm + sb + 4096 + arr * 2048 + wd), src);
            }
        }
    }
    CP_COMMIT();
    CP_WAIT0();
    __syncthreads();

    // ---- Q fragments to registers ----
    uint32_t qfh[4][4], qfl[4][4];
#pragma unroll
    for (int ks = 0; ks < 4; ++ks)
#pragma unroll
        for (int r = 0; r < 4; ++r) {
            int wd = (((w * 4 + ks) * 4 + r) << 5) + lane;
            qfh[ks][r] = dsm[8192 + wd];
            qfl[ks][r] = dsm[12288 + wd];
        }
    __syncthreads();   // Q region now free for stage1

    // ---- state ----
    float acc[8][4];
#pragma unroll
    for (int j = 0; j < 8; ++j)
#pragma unroll
        for (int r = 0; r < 4; ++r) acc[j][r] = 0.f;
    float m0 = -1e30f, m1 = -1e30f, l0 = 0.f, l1 = 0.f;

    const int q0w = qi * 128 + w * 16;        // warp's first q row (global)

    for (int kt = 0; kt <= kt_last; ++kt) {
        const int sb = (kt & 1) * 8192;
        if (kt < kt_last) {
            const int nkt = kt + 1;
            const int nsb = (nkt & 1) * 8192;
#pragma unroll
            for (int i = 0; i < 8; ++i) {
                int c = tid + i * 256;
                if (c < 1024) {
                    int arr = c >> 9, cc = c & 511;
                    int t = cc >> 3, kq = cc & 7;
                    int wd = ((((t >> 3) * 4 + (kq >> 1)) * 2 + (kq & 1)) << 5) + (t & 7) * 4;
                    const __nv_bfloat16* src = (arr ? Kl : Kh)
                        + (size_t)(b * SS + nkt * 64 + t) * D_MODEL + hoff + kq * 8;
                    CP_ASYNC16(smem_u32(dsm + nsb + arr * 2048 + wd), src);
                } else {
                    int c2 = c - 1024;
                    int arr = c2 >> 9, cc = c2 & 511;
                    int d = cc >> 3, tq = cc & 7;
                    int wd = ((((d >> 3) * 4 + (tq >> 1)) * 2 + (tq & 1)) << 5) + (d & 7) * 4;
                    const __nv_bfloat16* src = (arr ? Vtl : Vth)
                        + vrow0 + (size_t)d * SS + nkt * 64 + tq * 8;
                    CP_ASYNC16(smem_u32(dsm + nsb + 4096 + arr * 2048 + wd), src);
                }
            }
            CP_COMMIT();
            CP_WAIT1();
        } else {
            CP_WAIT0();
        }
        __syncthreads();

        if (kt * 64 <= q0w + 15) {   // warp has at least one unmasked row
            const uint32_t* sKh = dsm + sb;
            const uint32_t* sKl = dsm + sb + 2048;
            const uint32_t* sVh = dsm + sb + 4096;
            const uint32_t* sVl = dsm + sb + 6144;

            // ---- S = Q K^T (bf16x3) ----
            float s[8][4];
#pragma unroll
            for (int j = 0; j < 8; ++j)
#pragma unroll
                for (int r = 0; r < 4; ++r) s[j][r] = 0.f;

#pragma unroll
            for (int ks = 0; ks < 4; ++ks)
#pragma unroll
                for (int jn = 0; jn < 8; ++jn) {
                    int base = ((jn * 4 + ks) << 6) + lane;
                    uint32_t bh[2] = {sKh[base], sKh[base + 32]};
                    uint32_t bl[2] = {sKl[base], sKl[base + 32]};
                    mma_bf16(s[jn], qfh[ks], bh);
                    mma_bf16(s[jn], qfh[ks], bl);
                    mma_bf16(s[jn], qfl[ks], bh);
                }

#pragma unroll
            for (int j = 0; j < 8; ++j)
#pragma unroll
                for (int r = 0; r < 4; ++r) s[j][r] *= 0.125f;

            // ---- causal mask (diagonal tiles only) ----
            if (kt * 64 + 63 > q0w) {
                const int row0g = q0w + (lane >> 2);
                const int colbg = kt * 64 + 2 * (lane & 3);
#pragma unroll
                for (int jn = 0; jn < 8; ++jn) {
                    int c0 = colbg + jn * 8;
                    if (c0 > row0g)     s[jn][0] = -1e30f;
                    if (c0 + 1 > row0g) s[jn][1] = -1e30f;
                    if (c0 > row0g + 8)     s[jn][2] = -1e30f;
                    if (c0 + 1 > row0g + 8) s[jn][3] = -1e30f;
                }
            }

            // ---- online softmax (row groups = 4 lanes) ----
            float mx0 = -1e30f, mx1 = -1e30f;
#pragma unroll
            for (int j = 0; j < 8; ++j) {
                mx0 = fmaxf(mx0, fmaxf(s[j][0], s[j][1]));
                mx1 = fmaxf(mx1, fmaxf(s[j][2], s[j][3]));
            }
            mx0 = fmaxf(mx0, __shfl_xor_sync(0xffffffffu, mx0, 1));
            mx0 = fmaxf(mx0, __shfl_xor_sync(0xffffffffu, mx0, 2));
            mx1 = fmaxf(mx1, __shfl_xor_sync(0xffffffffu, mx1, 1));
            mx1 = fmaxf(mx1, __shfl_xor_sync(0xffffffffu, mx1, 2));

            float mn0 = fmaxf(m0, mx0), mn1 = fmaxf(m1, mx1);
            float al0 = __expf(m0 - mn0), al1 = __expf(m1 - mn1);
            m0 = mn0; m1 = mn1;

            float sum0 = 0.f, sum1 = 0.f;
#pragma unroll
            for (int j = 0; j < 8; ++j) {
                s[j][0] = __expf(s[j][0] - mn0);
                s[j][1] = __expf(s[j][1] - mn0);
                s[j][2] = __expf(s[j][2] - mn1);
                s[j][3] = __expf(s[j][3] - mn1);
                sum0 += s[j][0] + s[j][1];
                sum1 += s[j][2] + s[j][3];
            }
            sum0 += __shfl_xor_sync(0xffffffffu, sum0, 1);
            sum0 += __shfl_xor_sync(0xffffffffu, sum0, 2);
            sum1 += __shfl_xor_sync(0xffffffffu, sum1, 1);
            sum1 += __shfl_xor_sync(0xffffffffu, sum1, 2);
            l0 = l0 * al0 + sum0;
            l1 = l1 * al1 + sum1;

#pragma unroll
            for (int j = 0; j < 8; ++j) {
                acc[j][0] *= al0; acc[j][1] *= al0;
                acc[j][2] *= al1; acc[j][3] *= al1;
            }

            // ---- pack P into A fragments (hi/lo) ----
            uint32_t ph[4][4], pl[4][4];
#pragma unroll
            for (int kk = 0; kk < 4; ++kk) {
                split2(s[2 * kk][0],     s[2 * kk][1],     ph[kk][0], pl[kk][0]);
                split2(s[2 * kk][2],     s[2 * kk][3],     ph[kk][1], pl[kk][1]);
                split2(s[2 * kk + 1][0], s[2 * kk + 1][1], ph[kk][2], pl[kk][2]);
                split2(s[2 * kk + 1][2], s[2 * kk + 1][3], ph[kk][3], pl[kk][3]);
            }

            // ---- O += P V (bf16x3) ----
#pragma unroll
            for (int kk = 0; kk < 4; ++kk)
#pragma unroll
                for (int jd = 0; jd < 8; ++jd) {
                    int base = ((jd * 4 + kk) << 6) + lane;
                    uint32_t vh[2] = {sVh[base], sVh[base + 32]};
                    uint32_t vl[2] = {sVl[base], sVl[base + 32]};
                    mma_bf16(acc[jd], ph[kk], vh);
                    mma_bf16(acc[jd], ph[kk], vl);
                    mma_bf16(acc[jd], pl[kk], vh);
                }
        }
        __syncthreads();
    }

    // ---- epilogue ----
    const float inv0 = 1.f / l0, inv1 = 1.f / l1;
    const int r  = lane >> 2;
    const int cc = 2 * (lane & 3);
    float* o0 = O + (size_t)(tok0 + w * 16 + r) * D_MODEL + hoff;
    float* o1 = o0 + 8 * (size_t)D_MODEL;
#pragma unroll
    for (int jd = 0; jd < 8; ++jd) {
        *(float2*)(o0 + jd * 8 + cc) = make_float2(acc[jd][0] * inv0, acc[jd][1] * inv0);
        *(float2*)(o1 + jd * 8 + cc) = make_float2(acc[jd][2] * inv1, acc[jd][3] * inv1);
    }
}

// ---------------------------------------------------------------------------
extern "C" void kernel_launch(void* const* d_in, const int* in_sizes, int n_in,
                              void* d_out, int out_size)
{
    const float* wq  = (const float*)d_in[0];
    const float* wk  = (const float*)d_in[1];
    const float* wv  = (const float*)d_in[2];
    const float* wo  = (const float*)d_in[3];
    const float* x   = (const float*)d_in[4];
    const int*   pos = (const int*)d_in[5];
    float* out = (float*)d_out;

    float *dq, *dk, *dv, *datt;
    cudaGetSymbolAddress((void**)&dq,   g_q);
    cudaGetSymbolAddress((void**)&dk,   g_k);
    cudaGetSymbolAddress((void**)&dv,   g_v);
    cudaGetSymbolAddress((void**)&datt, g_att);
    __nv_bfloat16 *xh, *xl, *ath, *atl, *wh, *wl;
    __nv_bfloat16 *qh, *ql, *kh, *kl, *vth, *vtl;
    cudaGetSymbolAddress((void**)&xh,  g_xh);
    cudaGetSymbolAddress((void**)&xl,  g_xl);
    cudaGetSymbolAddress((void**)&ath, g_ah);
    cudaGetSymbolAddress((void**)&atl, g_al);
    cudaGetSymbolAddress((void**)&wh,  g_wh);
    cudaGetSymbolAddress((void**)&wl,  g_wl);
    cudaGetSymbolAddress((void**)&qh,  g_qh);
    cudaGetSymbolAddress((void**)&ql,  g_ql);
    cudaGetSymbolAddress((void**)&kh,  g_kh);
    cudaGetSymbolAddress((void**)&kl,  g_kl);
    cudaGetSymbolAddress((void**)&vth, g_vth);
    cudaGetSymbolAddress((void**)&vtl, g_vtl);

    const size_t WSZ = (size_t)D_MODEL * D_MODEL;
    const int n4x = (int)((size_t)MM * D_MODEL / 4);
    const int n4w = (int)(WSZ / 4);

    split_bf16_kernel<<<(n4x + 255) / 256, 256>>>(x, xh, xl, n4x);
    split_bf16_kernel<<<(n4w + 255) / 256, 256>>>(wq, wh + 0 * WSZ, wl + 0 * WSZ, n4w);
    split_bf16_kernel<<<(n4w + 255) / 256, 256>>>(wk, wh + 1 * WSZ, wl + 1 * WSZ, n4w);
    split_bf16_kernel<<<(n4w + 255) / 256, 256>>>(wv, wh + 2 * WSZ, wl + 2 * WSZ, n4w);
    split_bf16_kernel<<<(n4w + 255) / 256, 256>>>(wo, wh + 3 * WSZ, wl + 3 * WSZ, n4w);

    dim3 gg(D_MODEL / 128, MM / 128);  // (8, 64)

    gemm_bf16x3_nt<<<gg, 256>>>(xh, xl, wh + 0 * WSZ, wl + 0 * WSZ, dq, MM, D_MODEL, D_MODEL);
    gemm_bf16x3_nt<<<gg, 256>>>(xh, xl, wh + 1 * WSZ, wl + 1 * WSZ, dk, MM, D_MODEL, D_MODEL);
    gemm_bf16x3_nt<<<gg, 256>>>(xh, xl, wh + 2 * WSZ, wl + 2 * WSZ, dv, MM, D_MODEL, D_MODEL);

    const int rope_total = MM * NUM_HEADS * HALF;  // 4,194,304
    rope_split_kernel<<<rope_total / 256, 256>>>(dq, dk, pos, qh, ql, kh, kl);
    vtrans_split_kernel<<<dim3(SS / 64, BB * NUM_HEADS), 256>>>(dv, vth, vtl);

    cudaFuncSetAttribute(attn_tc_kernel,
                         cudaFuncAttributeMaxDynamicSharedMemorySize, 65536);
    attn_tc_kernel<<<dim3(SS / 128, NUM_HEADS, BB), 256, 65536>>>(
        qh, ql, kh, kl, vth, vtl, datt);

    split_bf16_kernel<<<(n4x + 255) / 256, 256>>>(datt, ath, atl, n4x);
    gemm_bf16x3_nt<<<gg, 256>>>(ath, atl, wh + 3 * WSZ, wl + 3 * WSZ, out, MM, D_MODEL, D_MODEL);
}

// round 7
// speedup vs baseline: 2.4556x; 1.0756x over previous
#include <cuda_runtime.h>
#include <cuda_bf16.h>
#include <math.h>
#include <stdint.h>

#define D_MODEL 1024
#define NUM_HEADS 16
#define DK 64
#define HALF 32
#define BB 4
#define SS 2048
#define MM (BB * SS)           // 8192 tokens
#define LOG2_THETA 13.287712379549449f   // log2(10000)

// ---------------- scratch (device globals: no allocation allowed) ----------
__device__ float g_qkv[3][(size_t)MM * D_MODEL];   // q, k, v projections (fp32)
__device__ float g_att[(size_t)MM * D_MODEL];

__device__ __nv_bfloat16 g_xh[(size_t)MM * D_MODEL];
__device__ __nv_bfloat16 g_xl[(size_t)MM * D_MODEL];
__device__ __nv_bfloat16 g_ah[(size_t)MM * D_MODEL];
__device__ __nv_bfloat16 g_al[(size_t)MM * D_MODEL];
__device__ __nv_bfloat16 g_wh[4][(size_t)D_MODEL * D_MODEL];
__device__ __nv_bfloat16 g_wl[4][(size_t)D_MODEL * D_MODEL];

__device__ __nv_bfloat16 g_qh[(size_t)MM * D_MODEL];
__device__ __nv_bfloat16 g_ql[(size_t)MM * D_MODEL];
__device__ __nv_bfloat16 g_kh[(size_t)MM * D_MODEL];
__device__ __nv_bfloat16 g_kl[(size_t)MM * D_MODEL];
__device__ __nv_bfloat16 g_vth[(size_t)MM * D_MODEL];  // [(b*16+h)*64+d][S]
__device__ __nv_bfloat16 g_vtl[(size_t)MM * D_MODEL];

// ---------------------------------------------------------------------------
__device__ __forceinline__ uint32_t smem_u32(const void* p) {
    return (uint32_t)__cvta_generic_to_shared(p);
}
#define CP_ASYNC16(dst, src) \
    asm volatile("cp.async.cg.shared.global [%0], [%1], 16;\n" :: "r"(dst), "l"(src))
#define CP_COMMIT() asm volatile("cp.async.commit_group;\n" ::: "memory")
#define CP_WAIT3()  asm volatile("cp.async.wait_group 3;\n" ::: "memory")
#define CP_WAIT2()  asm volatile("cp.async.wait_group 2;\n" ::: "memory")
#define CP_WAIT1()  asm volatile("cp.async.wait_group 1;\n" ::: "memory")
#define CP_WAIT0()  asm volatile("cp.async.wait_group 0;\n" ::: "memory")

__device__ __forceinline__ void mma_bf16(float c[4], const uint32_t a[4],
                                         const uint32_t b[2]) {
    asm volatile(
        "mma.sync.aligned.m16n8k16.row.col.f32.bf16.bf16.f32 "
        "{%0,%1,%2,%3}, {%4,%5,%6,%7}, {%8,%9}, {%0,%1,%2,%3};\n"
        : "+f"(c[0]), "+f"(c[1]), "+f"(c[2]), "+f"(c[3])
        : "r"(a[0]), "r"(a[1]), "r"(a[2]), "r"(a[3]), "r"(b[0]), "r"(b[1]));
}

__device__ __forceinline__ void split2(float x, float y, uint32_t& hi, uint32_t& lo) {
    __nv_bfloat162 h = __floats2bfloat162_rn(x, y);
    float hx = __bfloat162float(h.x), hy = __bfloat162float(h.y);
    __nv_bfloat162 l = __floats2bfloat162_rn(x - hx, y - hy);
    hi = *(uint32_t*)&h;
    lo = *(uint32_t*)&l;
}

// ---------------------------------------------------------------------------
// fp32 -> (bf16 hi, bf16 lo) split.
// ---------------------------------------------------------------------------
__global__ void __launch_bounds__(256) split_bf16_kernel(
    const float* __restrict__ src, __nv_bfloat16* __restrict__ hi,
    __nv_bfloat16* __restrict__ lo, int n4)
{
    int i = blockIdx.x * blockDim.x + threadIdx.x;
    if (i >= n4) return;
    float4 v = ((const float4*)src)[i];
    uint32_t h0, l0, h1, l1;
    split2(v.x, v.y, h0, l0);
    split2(v.z, v.w, h1, l1);
    ((uint32_t*)hi)[i * 2 + 0] = h0;
    ((uint32_t*)hi)[i * 2 + 1] = h1;
    ((uint32_t*)lo)[i * 2 + 0] = l0;
    ((uint32_t*)lo)[i * 2 + 1] = l1;
}

// ---------------------------------------------------------------------------
// bf16x3 mma.sync GEMM (NT), 4-stage cp.async, fused over blockIdx.z:
//   C_z[M,N] = (Ah+Al)[M,K] * (Wh_z + Wl_z)[N,K]^T
// 128x128 tile, BK=16, 256 threads (8 warps, 2x4), warp tile 64x32.
// Dynamic smem 64KB: 4 stages x (Ah|Al|Bh|Bl, 4KB each).
// Fragment-order smem -> lane-linear conflict-free LDS.32.
// ---------------------------------------------------------------------------
__device__ __forceinline__ void load_stage4(
    const __nv_bfloat16* __restrict__ gAh, const __nv_bfloat16* __restrict__ gAl,
    const __nv_bfloat16* __restrict__ gBh, const __nv_bfloat16* __restrict__ gBl,
    int Kdim, int k0, uint32_t* sb, int tid)
{
    const int m = tid >> 1;
    const int q = tid & 1;
    const size_t src = (size_t)m * Kdim + k0 + q * 8;
    const int aw = ((((m >> 4) * 4 + ((m >> 3) & 1) + 2 * q)) << 5) + (m & 7) * 4;
    const int bw = ((((m >> 3) * 2 + q)) << 5) + (m & 7) * 4;
    CP_ASYNC16(smem_u32(sb + aw),        gAh + src);
    CP_ASYNC16(smem_u32(sb + 1024 + aw), gAl + src);
    CP_ASYNC16(smem_u32(sb + 2048 + bw), gBh + src);
    CP_ASYNC16(smem_u32(sb + 3072 + bw), gBl + src);
}

__global__ void __launch_bounds__(256) gemm_bf16x3_nt(
    const __nv_bfloat16* __restrict__ Ah, const __nv_bfloat16* __restrict__ Al,
    const __nv_bfloat16* __restrict__ WhB, const __nv_bfloat16* __restrict__ WlB,
    float* __restrict__ Cb, int Mdim, int Ndim, int Kdim)
{
    extern __shared__ uint32_t smem4[];   // 4 stages x 4096 u32 = 64KB

    const int tid  = threadIdx.x;
    const int lane = tid & 31;
    const int warp = tid >> 5;
    const int wy   = warp >> 2;
    const int wx   = warp & 3;
    const int row0 = blockIdx.y * 128;
    const int col0 = blockIdx.x * 128;
    const size_t zw = (size_t)blockIdx.z * D_MODEL * D_MODEL;

    const __nv_bfloat16* gAh = Ah + (size_t)row0 * Kdim;
    const __nv_bfloat16* gAl = Al + (size_t)row0 * Kdim;
    const __nv_bfloat16* gBh = WhB + zw + (size_t)col0 * Kdim;
    const __nv_bfloat16* gBl = WlB + zw + (size_t)col0 * Kdim;
    float* C = Cb + (size_t)blockIdx.z * Mdim * Ndim;

    float c[4][4][4];
#pragma unroll
    for (int i = 0; i < 4; ++i)
#pragma unroll
        for (int j = 0; j < 4; ++j)
#pragma unroll
            for (int r = 0; r < 4; ++r) c[i][j][r] = 0.f;

    const int NT = Kdim / 16;             // 64
    load_stage4(gAh, gAl, gBh, gBl, Kdim, 0,  smem4,        tid); CP_COMMIT();
    load_stage4(gAh, gAl, gBh, gBl, Kdim, 16, smem4 + 4096, tid); CP_COMMIT();
    load_stage4(gAh, gAl, gBh, gBl, Kdim, 32, smem4 + 8192, tid); CP_COMMIT();

    for (int t = 0; t < NT; ++t) {
        if (t + 3 < NT) {
            load_stage4(gAh, gAl, gBh, gBl, Kdim, (t + 3) * 16,
                        smem4 + ((t + 3) & 3) * 4096, tid);
            CP_COMMIT();
            CP_WAIT3();
        } else if (t + 2 < NT) { CP_WAIT2(); }
        else if   (t + 1 < NT) { CP_WAIT1(); }
        else                   { CP_WAIT0(); }
        __syncthreads();

        const uint32_t* sb  = smem4 + (t & 3) * 4096;
        const uint32_t* pAh = sb;
        const uint32_t* pAl = sb + 1024;
        const uint32_t* pBh = sb + 2048;
        const uint32_t* pBl = sb + 3072;

        uint32_t ah[4][4], al[4][4], bh[4][2], bl[4][2];
#pragma unroll
        for (int i = 0; i < 4; ++i) {
            const int base = (((wy * 4 + i) * 4) << 5) + lane;
#pragma unroll
            for (int r = 0; r < 4; ++r) {
                ah[i][r] = pAh[base + (r << 5)];
                al[i][r] = pAl[base + (r << 5)];
            }
        }
#pragma unroll
        for (int j = 0; j < 4; ++j) {
            const int base = (((wx * 4 + j) * 2) << 5) + lane;
#pragma unroll
            for (int r = 0; r < 2; ++r) {
                bh[j][r] = pBh[base + (r << 5)];
                bl[j][r] = pBl[base + (r << 5)];
            }
        }

#pragma unroll
        for (int i = 0; i < 4; ++i)
#pragma unroll
            for (int j = 0; j < 4; ++j) {
                mma_bf16(c[i][j], ah[i], bh[j]);
                mma_bf16(c[i][j], ah[i], bl[j]);
                mma_bf16(c[i][j], al[i], bh[j]);
            }
        __syncthreads();
    }

    const int r  = lane >> 2;
    const int cc = (lane & 3) * 2;
#pragma unroll
    for (int i = 0; i < 4; ++i)
#pragma unroll
        for (int j = 0; j < 4; ++j) {
            float* cp = C + (size_t)(row0 + wy * 64 + i * 16 + r) * Ndim
                          + col0 + wx * 32 + j * 8 + cc;
            *(float2*)cp = make_float2(c[i][j][0], c[i][j][1]);
            *(float2*)(cp + 8 * (size_t)Ndim) = make_float2(c[i][j][2], c[i][j][3]);
        }
}

// ---------------------------------------------------------------------------
// RoPE + split: reads fp32 q,k; writes rotated bf16 hi/lo.
// ---------------------------------------------------------------------------
__global__ void __launch_bounds__(256) rope_split_kernel(
    const float* __restrict__ q, const float* __restrict__ k,
    const int* __restrict__ pos,
    __nv_bfloat16* __restrict__ qh, __nv_bfloat16* __restrict__ ql,
    __nv_bfloat16* __restrict__ kh, __nv_bfloat16* __restrict__ kl)
{
    const int idx = blockIdx.x * blockDim.x + threadIdx.x;
    const int i = idx & (HALF - 1);
    const int h = (idx >> 5) & (NUM_HEADS - 1);
    const int m = idx >> 9;
    const int s = m & (SS - 1);

    const float p = (float)pos[s];
    const float inv_freq = exp2f(-(float)i * (LOG2_THETA / (float)HALF));
    float sn, cs;
    sincosf(p * inv_freq, &sn, &cs);

    const size_t base = (size_t)m * D_MODEL + h * DK + 2 * i;

    float2 qv = *(const float2*)(q + base);
    float2 kv = *(const float2*)(k + base);
    float qe = qv.x * cs - qv.y * sn, qo = qv.x * sn + qv.y * cs;
    float ke = kv.x * cs - kv.y * sn, ko = kv.x * sn + kv.y * cs;

    uint32_t hh, ll;
    split2(qe, qo, hh, ll);
    *(uint32_t*)(qh + base) = hh; *(uint32_t*)(ql + base) = ll;
    split2(ke, ko, hh, ll);
    *(uint32_t*)(kh + base) = hh; *(uint32_t*)(kl + base) = ll;
}

// ---------------------------------------------------------------------------
// V transpose + split: fp32 [b*S+t][1024] -> vth/vtl [(b*16+h)*64+d][S]
// ---------------------------------------------------------------------------
__global__ void __launch_bounds__(256) vtrans_split_kernel(
    const float* __restrict__ v,
    __nv_bfloat16* __restrict__ vth, __nv_bfloat16* __restrict__ vtl)
{
    __shared__ float tile[64][65];
    const int tb = blockIdx.x;
    const int bh = blockIdx.y;
    const int b  = bh >> 4, h = bh & 15;
    const int tid = threadIdx.x;

#pragma unroll
    for (int i = 0; i < 4; ++i) {
        int e = tid + i * 256;
        int t = e >> 4;
        int d4 = (e & 15) * 4;
        float4 vv = *(const float4*)(v + (size_t)(b * SS + tb * 64 + t) * D_MODEL
                                       + h * DK + d4);
        tile[d4 + 0][t] = vv.x;
        tile[d4 + 1][t] = vv.y;
        tile[d4 + 2][t] = vv.z;
        tile[d4 + 3][t] = vv.w;
    }
    __syncthreads();

#pragma unroll
    for (int i = 0; i < 8; ++i) {
        int e = tid + i * 256;
        int d = e >> 5;
        int t2 = (e & 31) * 2;
        uint32_t hh, ll;
        split2(tile[d][t2], tile[d][t2 + 1], hh, ll);
        size_t dst = ((size_t)(bh * 64 + d)) * SS + tb * 64 + t2;
        *(uint32_t*)(vth + dst) = hh;
        *(uint32_t*)(vtl + dst) = ll;
    }
}

// ---------------------------------------------------------------------------
// Tensor-core flash attention (causal), bf16x3 — unchanged (validated R5).
// ---------------------------------------------------------------------------
__global__ void __launch_bounds__(256, 1) attn_tc_kernel(
    const __nv_bfloat16* __restrict__ Qh, const __nv_bfloat16* __restrict__ Ql,
    const __nv_bfloat16* __restrict__ Kh, const __nv_bfloat16* __restrict__ Kl,
    const __nv_bfloat16* __restrict__ Vth, const __nv_bfloat16* __restrict__ Vtl,
    float* __restrict__ O)
{
    extern __shared__ uint32_t dsm[];   // 16384 u32 = 64KB

    const int qi  = blockIdx.x;
    const int h   = blockIdx.y;
    const int b   = blockIdx.z;
    const int tid = threadIdx.x;
    const int lane = tid & 31;
    const int w    = tid >> 5;

    const int tok0 = b * SS + qi * 128;
    const int hoff = h * DK;
    const size_t vrow0 = (size_t)((b * 16 + h) * 64) * SS;
    const int kt_last = qi * 2 + 1;

#pragma unroll
    for (int i = 0; i < 8; ++i) {
        int c   = tid + i * 256;
        int arr = c >> 10;
        int cc  = c & 1023;
        int m = cc >> 3, kq = cc & 7;
        int wd = ((((m >> 4) * 4 + (kq >> 1)) * 4 + ((m >> 3) & 1) + 2 * (kq & 1)) << 5)
                 + (m & 7) * 4;
        const __nv_bfloat16* src = (arr ? Ql : Qh)
            + (size_t)(tok0 + m) * D_MODEL + hoff + kq * 8;
        CP_ASYNC16(smem_u32(dsm + 8192 + arr * 4096 + wd), src);
    }
    {
        const int kt = 0, sb = 0;
#pragma unroll
        for (int i = 0; i < 8; ++i) {
            int c = tid + i * 256;
            if (c < 1024) {
                int arr = c >> 9, cc = c & 511;
                int t = cc >> 3, kq = cc & 7;
                int wd = ((((t >> 3) * 4 + (kq >> 1)) * 2 + (kq & 1)) << 5) + (t & 7) * 4;
                const __nv_bfloat16* src = (arr ? Kl : Kh)
                    + (size_t)(b * SS + kt * 64 + t) * D_MODEL + hoff + kq * 8;
                CP_ASYNC16(smem_u32(dsm + sb + arr * 2048 + wd), src);
            } else {
                int c2 = c - 1024;
                int arr = c2 >> 9, cc = c2 & 511;
                int d = cc >> 3, tq = cc & 7;
                int wd = ((((d >> 3) * 4 + (tq >> 1)) * 2 + (tq & 1)) << 5) + (d & 7) * 4;
                const __nv_bfloat16* src = (arr ? Vtl : Vth)
                    + vrow0 + (size_t)d * SS + kt * 64 + tq * 8;
                CP_ASYNC16(smem_u32(dsm + sb + 4096 + arr * 2048 + wd), src);
            }
        }
    }
    CP_COMMIT();
    CP_WAIT0();
    __syncthreads();

    uint32_t qfh[4][4], qfl[4][4];
#pragma unroll
    for (int ks = 0; ks < 4; ++ks)
#pragma unroll
        for (int r = 0; r < 4; ++r) {
            int wd = (((w * 4 + ks) * 4 + r) << 5) + lane;
            qfh[ks][r] = dsm[8192 + wd];
            qfl[ks][r] = dsm[12288 + wd];
        }
    __syncthreads();

    float acc[8][4];
#pragma unroll
    for (int j = 0; j < 8; ++j)
#pragma unroll
        for (int r = 0; r < 4; ++r) acc[j][r] = 0.f;
    float m0 = -1e30f, m1 = -1e30f, l0 = 0.f, l1 = 0.f;

    const int q0w = qi * 128 + w * 16;

    for (int kt = 0; kt <= kt_last; ++kt) {
        const int sb = (kt & 1) * 8192;
        if (kt < kt_last) {
            const int nkt = kt + 1;
            const int nsb = (nkt & 1) * 8192;
#pragma unroll
            for (int i = 0; i < 8; ++i) {
                int c = tid + i * 256;
                if (c < 1024) {
                    int arr = c >> 9, cc = c & 511;
                    int t = cc >> 3, kq = cc & 7;
                    int wd = ((((t >> 3) * 4 + (kq >> 1)) * 2 + (kq & 1)) << 5) + (t & 7) * 4;
                    const __nv_bfloat16* src = (arr ? Kl : Kh)
                        + (size_t)(b * SS + nkt * 64 + t) * D_MODEL + hoff + kq * 8;
                    CP_ASYNC16(smem_u32(dsm + nsb + arr * 2048 + wd), src);
                } else {
                    int c2 = c - 1024;
                    int arr = c2 >> 9, cc = c2 & 511;
                    int d = cc >> 3, tq = cc & 7;
                    int wd = ((((d >> 3) * 4 + (tq >> 1)) * 2 + (tq & 1)) << 5) + (d & 7) * 4;
                    const __nv_bfloat16* src = (arr ? Vtl : Vth)
                        + vrow0 + (size_t)d * SS + nkt * 64 + tq * 8;
                    CP_ASYNC16(smem_u32(dsm + nsb + 4096 + arr * 2048 + wd), src);
                }
            }
            CP_COMMIT();
            CP_WAIT1();
        } else {
            CP_WAIT0();
        }
        __syncthreads();

        if (kt * 64 <= q0w + 15) {
            const uint32_t* sKh = dsm + sb;
            const uint32_t* sKl = dsm + sb + 2048;
            const uint32_t* sVh = dsm + sb + 4096;
            const uint32_t* sVl = dsm + sb + 6144;

            float s[8][4];
#pragma unroll
            for (int j = 0; j < 8; ++j)
#pragma unroll
                for (int r = 0; r < 4; ++r) s[j][r] = 0.f;

#pragma unroll
            for (int ks = 0; ks < 4; ++ks)
#pragma unroll
                for (int jn = 0; jn < 8; ++jn) {
                    int base = ((jn * 4 + ks) << 6) + lane;
                    uint32_t bh[2] = {sKh[base], sKh[base + 32]};
                    uint32_t bl[2] = {sKl[base], sKl[base + 32]};
                    mma_bf16(s[jn], qfh[ks], bh);
                    mma_bf16(s[jn], qfh[ks], bl);
                    mma_bf16(s[jn], qfl[ks], bh);
                }

#pragma unroll
            for (int j = 0; j < 8; ++j)
#pragma unroll
                for (int r = 0; r < 4; ++r) s[j][r] *= 0.125f;

            if (kt * 64 + 63 > q0w) {
                const int row0g = q0w + (lane >> 2);
                const int colbg = kt * 64 + 2 * (lane & 3);
#pragma unroll
                for (int jn = 0; jn < 8; ++jn) {
                    int c0 = colbg + jn * 8;
                    if (c0 > row0g)     s[jn][0] = -1e30f;
                    if (c0 + 1 > row0g) s[jn][1] = -1e30f;
                    if (c0 > row0g + 8)     s[jn][2] = -1e30f;
                    if (c0 + 1 > row0g + 8) s[jn][3] = -1e30f;
                }
            }

            float mx0 = -1e30f, mx1 = -1e30f;
#pragma unroll
            for (int j = 0; j < 8; ++j) {
                mx0 = fmaxf(mx0, fmaxf(s[j][0], s[j][1]));
                mx1 = fmaxf(mx1, fmaxf(s[j][2], s[j][3]));
            }
            mx0 = fmaxf(mx0, __shfl_xor_sync(0xffffffffu, mx0, 1));
            mx0 = fmaxf(mx0, __shfl_xor_sync(0xffffffffu, mx0, 2));
            mx1 = fmaxf(mx1, __shfl_xor_sync(0xffffffffu, mx1, 1));
            mx1 = fmaxf(mx1, __shfl_xor_sync(0xffffffffu, mx1, 2));

            float mn0 = fmaxf(m0, mx0), mn1 = fmaxf(m1, mx1);
            float al0 = __expf(m0 - mn0), al1 = __expf(m1 - mn1);
            m0 = mn0; m1 = mn1;

            float sum0 = 0.f, sum1 = 0.f;
#pragma unroll
            for (int j = 0; j < 8; ++j) {
                s[j][0] = __expf(s[j][0] - mn0);
                s[j][1] = __expf(s[j][1] - mn0);
                s[j][2] = __expf(s[j][2] - mn1);
                s[j][3] = __expf(s[j][3] - mn1);
                sum0 += s[j][0] + s[j][1];
                sum1 += s[j][2] + s[j][3];
            }
            sum0 += __shfl_xor_sync(0xffffffffu, sum0, 1);
            sum0 += __shfl_xor_sync(0xffffffffu, sum0, 2);
            sum1 += __shfl_xor_sync(0xffffffffu, sum1, 1);
            sum1 += __shfl_xor_sync(0xffffffffu, sum1, 2);
            l0 = l0 * al0 + sum0;
            l1 = l1 * al1 + sum1;

#pragma unroll
            for (int j = 0; j < 8; ++j) {
                acc[j][0] *= al0; acc[j][1] *= al0;
                acc[j][2] *= al1; acc[j][3] *= al1;
            }

            uint32_t ph[4][4], pl[4][4];
#pragma unroll
            for (int kk = 0; kk < 4; ++kk) {
                split2(s[2 * kk][0],     s[2 * kk][1],     ph[kk][0], pl[kk][0]);
                split2(s[2 * kk][2],     s[2 * kk][3],     ph[kk][1], pl[kk][1]);
                split2(s[2 * kk + 1][0], s[2 * kk + 1][1], ph[kk][2], pl[kk][2]);
                split2(s[2 * kk + 1][2], s[2 * kk + 1][3], ph[kk][3], pl[kk][3]);
            }

#pragma unroll
            for (int kk = 0; kk < 4; ++kk)
#pragma unroll
                for (int jd = 0; jd < 8; ++jd) {
                    int base = ((jd * 4 + kk) << 6) + lane;
                    uint32_t vh[2] = {sVh[base], sVh[base + 32]};
                    uint32_t vl[2] = {sVl[base], sVl[base + 32]};
                    mma_bf16(acc[jd], ph[kk], vh);
                    mma_bf16(acc[jd], ph[kk], vl);
                    mma_bf16(acc[jd], pl[kk], vh);
                }
        }
        __syncthreads();
    }

    const float inv0 = 1.f / l0, inv1 = 1.f / l1;
    const int r  = lane >> 2;
    const int cc = 2 * (lane & 3);
    float* o0 = O + (size_t)(tok0 + w * 16 + r) * D_MODEL + hoff;
    float* o1 = o0 + 8 * (size_t)D_MODEL;
#pragma unroll
    for (int jd = 0; jd < 8; ++jd) {
        *(float2*)(o0 + jd * 8 + cc) = make_float2(acc[jd][0] * inv0, acc[jd][1] * inv0);
        *(float2*)(o1 + jd * 8 + cc) = make_float2(acc[jd][2] * inv1, acc[jd][3] * inv1);
    }
}

// ---------------------------------------------------------------------------
extern "C" void kernel_launch(void* const* d_in, const int* in_sizes, int n_in,
                              void* d_out, int out_size)
{
    const float* wq  = (const float*)d_in[0];
    const float* wk  = (const float*)d_in[1];
    const float* wv  = (const float*)d_in[2];
    const float* wo  = (const float*)d_in[3];
    const float* x   = (const float*)d_in[4];
    const int*   pos = (const int*)d_in[5];
    float* out = (float*)d_out;

    float *dqkv, *datt;
    cudaGetSymbolAddress((void**)&dqkv, g_qkv);
    cudaGetSymbolAddress((void**)&datt, g_att);
    __nv_bfloat16 *xh, *xl, *ath, *atl, *wh, *wl;
    __nv_bfloat16 *qh, *ql, *kh, *kl, *vth, *vtl;
    cudaGetSymbolAddress((void**)&xh,  g_xh);
    cudaGetSymbolAddress((void**)&xl,  g_xl);
    cudaGetSymbolAddress((void**)&ath, g_ah);
    cudaGetSymbolAddress((void**)&atl, g_al);
    cudaGetSymbolAddress((void**)&wh,  g_wh);
    cudaGetSymbolAddress((void**)&wl,  g_wl);
    cudaGetSymbolAddress((void**)&qh,  g_qh);
    cudaGetSymbolAddress((void**)&ql,  g_ql);
    cudaGetSymbolAddress((void**)&kh,  g_kh);
    cudaGetSymbolAddress((void**)&kl,  g_kl);
    cudaGetSymbolAddress((void**)&vth, g_vth);
    cudaGetSymbolAddress((void**)&vtl, g_vtl);

    float* dq = dqkv;
    float* dk = dqkv + (size_t)MM * D_MODEL;
    float* dv = dqkv + 2 * (size_t)MM * D_MODEL;

    const size_t WSZ = (size_t)D_MODEL * D_MODEL;
    const int n4x = (int)((size_t)MM * D_MODEL / 4);
    const int n4w = (int)(WSZ / 4);

    split_bf16_kernel<<<(n4x + 255) / 256, 256>>>(x, xh, xl, n4x);
    split_bf16_kernel<<<(n4w + 255) / 256, 256>>>(wq, wh + 0 * WSZ, wl + 0 * WSZ, n4w);
    split_bf16_kernel<<<(n4w + 255) / 256, 256>>>(wk, wh + 1 * WSZ, wl + 1 * WSZ, n4w);
    split_bf16_kernel<<<(n4w + 255) / 256, 256>>>(wv, wh + 2 * WSZ, wl + 2 * WSZ, n4w);
    split_bf16_kernel<<<(n4w + 255) / 256, 256>>>(wo, wh + 3 * WSZ, wl + 3 * WSZ, n4w);

    cudaFuncSetAttribute(gemm_bf16x3_nt,
                         cudaFuncAttributeMaxDynamicSharedMemorySize, 65536);

    // fused QKV: grid.z picks weight (z*WSZ) and output slab (z*MM*D)
    gemm_bf16x3_nt<<<dim3(D_MODEL / 128, MM / 128, 3), 256, 65536>>>(
        xh, xl, wh, wl, dqkv, MM, D_MODEL, D_MODEL);

    const int rope_total = MM * NUM_HEADS * HALF;
    rope_split_kernel<<<rope_total / 256, 256>>>(dq, dk, pos, qh, ql, kh, kl);
    vtrans_split_kernel<<<dim3(SS / 64, BB * NUM_HEADS), 256>>>(dv, vth, vtl);

    cudaFuncSetAttribute(attn_tc_kernel,
                         cudaFuncAttributeMaxDynamicSharedMemorySize, 65536);
    attn_tc_kernel<<<dim3(SS / 128, NUM_HEADS, BB), 256, 65536>>>(
        qh, ql, kh, kl, vth, vtl, datt);

    split_bf16_kernel<<<(n4x + 255) / 256, 256>>>(datt, ath, atl, n4x);
    // O projection: single-z launch with weight slot 3
    gemm_bf16x3_nt<<<dim3(D_MODEL / 128, MM / 128, 1), 256, 65536>>>(
        ath, atl, wh + 3 * WSZ, wl + 3 * WSZ, out, MM, D_MODEL, D_MODEL);
}

// round 8
// speedup vs baseline: 2.4940x; 1.0156x over previous
#include <cuda_runtime.h>
#include <cuda_bf16.h>
#include <math.h>
#include <stdint.h>

#define D_MODEL 1024
#define NUM_HEADS 16
#define DK 64
#define HALF 32
#define BB 4
#define SS 2048
#define MM (BB * SS)           // 8192 tokens
#define LOG2_THETA 13.287712379549449f   // log2(10000)

// ---------------- scratch (device globals: no allocation allowed) ----------
__device__ float g_v[(size_t)MM * D_MODEL];            // V projection (fp32)

__device__ __nv_bfloat16 g_xh[(size_t)MM * D_MODEL];
__device__ __nv_bfloat16 g_xl[(size_t)MM * D_MODEL];
__device__ __nv_bfloat16 g_ah[(size_t)MM * D_MODEL];   // attention out hi
__device__ __nv_bfloat16 g_al[(size_t)MM * D_MODEL];   // attention out lo
__device__ __nv_bfloat16 g_wh[4][(size_t)D_MODEL * D_MODEL];
__device__ __nv_bfloat16 g_wl[4][(size_t)D_MODEL * D_MODEL];

__device__ __nv_bfloat16 g_qh[(size_t)MM * D_MODEL];
__device__ __nv_bfloat16 g_ql[(size_t)MM * D_MODEL];
__device__ __nv_bfloat16 g_kh[(size_t)MM * D_MODEL];
__device__ __nv_bfloat16 g_kl[(size_t)MM * D_MODEL];
__device__ __nv_bfloat16 g_vth[(size_t)MM * D_MODEL];  // [(b*16+h)*64+d][S]
__device__ __nv_bfloat16 g_vtl[(size_t)MM * D_MODEL];

__device__ float2 g_rope[(size_t)SS * HALF];           // {cos, sin} table

// ---------------------------------------------------------------------------
__device__ __forceinline__ uint32_t smem_u32(const void* p) {
    return (uint32_t)__cvta_generic_to_shared(p);
}
#define CP_ASYNC16(dst, src) \
    asm volatile("cp.async.cg.shared.global [%0], [%1], 16;\n" :: "r"(dst), "l"(src))
#define CP_COMMIT() asm volatile("cp.async.commit_group;\n" ::: "memory")
#define CP_WAIT3()  asm volatile("cp.async.wait_group 3;\n" ::: "memory")
#define CP_WAIT2()  asm volatile("cp.async.wait_group 2;\n" ::: "memory")
#define CP_WAIT1()  asm volatile("cp.async.wait_group 1;\n" ::: "memory")
#define CP_WAIT0()  asm volatile("cp.async.wait_group 0;\n" ::: "memory")

__device__ __forceinline__ void mma_bf16(float c[4], const uint32_t a[4],
                                         const uint32_t b[2]) {
    asm volatile(
        "mma.sync.aligned.m16n8k16.row.col.f32.bf16.bf16.f32 "
        "{%0,%1,%2,%3}, {%4,%5,%6,%7}, {%8,%9}, {%0,%1,%2,%3};\n"
        : "+f"(c[0]), "+f"(c[1]), "+f"(c[2]), "+f"(c[3])
        : "r"(a[0]), "r"(a[1]), "r"(a[2]), "r"(a[3]), "r"(b[0]), "r"(b[1]));
}

__device__ __forceinline__ void split2(float x, float y, uint32_t& hi, uint32_t& lo) {
    __nv_bfloat162 h = __floats2bfloat162_rn(x, y);
    float hx = __bfloat162float(h.x), hy = __bfloat162float(h.y);
    __nv_bfloat162 l = __floats2bfloat162_rn(x - hx, y - hy);
    hi = *(uint32_t*)&h;
    lo = *(uint32_t*)&l;
}

// ---------------------------------------------------------------------------
// RoPE cos/sin table: tab[s*32 + i] = {cos, sin}(pos[s] * theta^(-i/32))
// ---------------------------------------------------------------------------
__global__ void __launch_bounds__(256) rope_table_kernel(
    const int* __restrict__ pos, float2* __restrict__ tab)
{
    int idx = blockIdx.x * blockDim.x + threadIdx.x;   // < SS*HALF
    int s = idx >> 5, i = idx & (HALF - 1);
    float p = (float)pos[s];
    float inv_freq = exp2f(-(float)i * (LOG2_THETA / (float)HALF));
    float sn, cs;
    sincosf(p * inv_freq, &sn, &cs);
    tab[idx] = make_float2(cs, sn);
}

// ---------------------------------------------------------------------------
// fp32 -> (bf16 hi, bf16 lo) split.
// ---------------------------------------------------------------------------
__global__ void __launch_bounds__(256) split_bf16_kernel(
    const float* __restrict__ src, __nv_bfloat16* __restrict__ hi,
    __nv_bfloat16* __restrict__ lo, int n4)
{
    int i = blockIdx.x * blockDim.x + threadIdx.x;
    if (i >= n4) return;
    float4 v = ((const float4*)src)[i];
    uint32_t h0, l0, h1, l1;
    split2(v.x, v.y, h0, l0);
    split2(v.z, v.w, h1, l1);
    ((uint32_t*)hi)[i * 2 + 0] = h0;
    ((uint32_t*)hi)[i * 2 + 1] = h1;
    ((uint32_t*)lo)[i * 2 + 0] = l0;
    ((uint32_t*)lo)[i * 2 + 1] = l1;
}

// ---------------------------------------------------------------------------
// bf16x3 mma.sync GEMM (NT), 4-stage cp.async.
// FUSED=1 (QKV): z=0 -> rope+split to qh/ql; z=1 -> rope+split to kh/kl;
//                z=2 -> fp32 to Cf (V).
// FUSED=0 (O-proj): plain fp32 epilogue to Cf.
// ---------------------------------------------------------------------------
__device__ __forceinline__ void load_stage4(
    const __nv_bfloat16* __restrict__ gAh, const __nv_bfloat16* __restrict__ gAl,
    const __nv_bfloat16* __restrict__ gBh, const __nv_bfloat16* __restrict__ gBl,
    int Kdim, int k0, uint32_t* sb, int tid)
{
    const int m = tid >> 1;
    const int q = tid & 1;
    const size_t src = (size_t)m * Kdim + k0 + q * 8;
    const int aw = ((((m >> 4) * 4 + ((m >> 3) & 1) + 2 * q)) << 5) + (m & 7) * 4;
    const int bw = ((((m >> 3) * 2 + q)) << 5) + (m & 7) * 4;
    CP_ASYNC16(smem_u32(sb + aw),        gAh + src);
    CP_ASYNC16(smem_u32(sb + 1024 + aw), gAl + src);
    CP_ASYNC16(smem_u32(sb + 2048 + bw), gBh + src);
    CP_ASYNC16(smem_u32(sb + 3072 + bw), gBl + src);
}

template <int FUSED>
__global__ void __launch_bounds__(256, 2) gemm_bf16x3_nt(
    const __nv_bfloat16* __restrict__ Ah, const __nv_bfloat16* __restrict__ Al,
    const __nv_bfloat16* __restrict__ WhB, const __nv_bfloat16* __restrict__ WlB,
    float* __restrict__ Cf,
    __nv_bfloat16* __restrict__ qh, __nv_bfloat16* __restrict__ ql,
    __nv_bfloat16* __restrict__ kh, __nv_bfloat16* __restrict__ kl,
    const float2* __restrict__ rope,
    int Mdim, int Ndim, int Kdim)
{
    extern __shared__ uint32_t smem4[];   // 4 stages x 4096 u32 = 64KB

    const int tid  = threadIdx.x;
    const int lane = tid & 31;
    const int warp = tid >> 5;
    const int wy   = warp >> 2;
    const int wx   = warp & 3;
    const int row0 = blockIdx.y * 128;
    const int col0 = blockIdx.x * 128;
    const int z    = blockIdx.z;
    const size_t zw = (size_t)z * D_MODEL * D_MODEL;

    const __nv_bfloat16* gAh = Ah + (size_t)row0 * Kdim;
    const __nv_bfloat16* gAl = Al + (size_t)row0 * Kdim;
    const __nv_bfloat16* gBh = WhB + zw + (size_t)col0 * Kdim;
    const __nv_bfloat16* gBl = WlB + zw + (size_t)col0 * Kdim;

    float c[4][4][4];
#pragma unroll
    for (int i = 0; i < 4; ++i)
#pragma unroll
        for (int j = 0; j < 4; ++j)
#pragma unroll
            for (int r = 0; r < 4; ++r) c[i][j][r] = 0.f;

    const int NT = Kdim / 16;             // 64
    load_stage4(gAh, gAl, gBh, gBl, Kdim, 0,  smem4,        tid); CP_COMMIT();
    load_stage4(gAh, gAl, gBh, gBl, Kdim, 16, smem4 + 4096, tid); CP_COMMIT();
    load_stage4(gAh, gAl, gBh, gBl, Kdim, 32, smem4 + 8192, tid); CP_COMMIT();

    for (int t = 0; t < NT; ++t) {
        if (t + 3 < NT) {
            load_stage4(gAh, gAl, gBh, gBl, Kdim, (t + 3) * 16,
                        smem4 + ((t + 3) & 3) * 4096, tid);
            CP_COMMIT();
            CP_WAIT3();
        } else if (t + 2 < NT) { CP_WAIT2(); }
        else if   (t + 1 < NT) { CP_WAIT1(); }
        else                   { CP_WAIT0(); }
        __syncthreads();

        const uint32_t* sb  = smem4 + (t & 3) * 4096;
        const uint32_t* pAh = sb;
        const uint32_t* pAl = sb + 1024;
        const uint32_t* pBh = sb + 2048;
        const uint32_t* pBl = sb + 3072;

        uint32_t ah[4][4], al[4][4], bh[4][2], bl[4][2];
#pragma unroll
        for (int i = 0; i < 4; ++i) {
            const int base = (((wy * 4 + i) * 4) << 5) + lane;
#pragma unroll
            for (int r = 0; r < 4; ++r) {
                ah[i][r] = pAh[base + (r << 5)];
                al[i][r] = pAl[base + (r << 5)];
            }
        }
#pragma unroll
        for (int j = 0; j < 4; ++j) {
            const int base = (((wx * 4 + j) * 2) << 5) + lane;
#pragma unroll
            for (int r = 0; r < 2; ++r) {
                bh[j][r] = pBh[base + (r << 5)];
                bl[j][r] = pBl[base + (r << 5)];
            }
        }

#pragma unroll
        for (int i = 0; i < 4; ++i)
#pragma unroll
            for (int j = 0; j < 4; ++j) {
                mma_bf16(c[i][j], ah[i], bh[j]);
                mma_bf16(c[i][j], ah[i], bl[j]);
                mma_bf16(c[i][j], al[i], bh[j]);
            }
        __syncthreads();
    }

    const int r  = lane >> 2;
    const int cc = (lane & 3) * 2;

    if (FUSED && z < 2) {
        // rope + hi/lo split epilogue for Q (z=0) / K (z=1)
        __nv_bfloat16* oh = z ? kh : qh;
        __nv_bfloat16* ol = z ? kl : ql;
#pragma unroll
        for (int i = 0; i < 4; ++i)
#pragma unroll
            for (int j = 0; j < 4; ++j) {
                const int col = col0 + wx * 32 + j * 8 + cc;       // even
                const int pi  = (col & 63) >> 1;                   // rope pair idx
                const int m0r = row0 + wy * 64 + i * 16 + r;
                const int m1r = m0r + 8;
                float2 t0 = rope[(size_t)(m0r & (SS - 1)) * HALF + pi];
                float2 t1 = rope[(size_t)(m1r & (SS - 1)) * HALF + pi];
                uint32_t hh, ll;
                float re0 = c[i][j][0] * t0.x - c[i][j][1] * t0.y;
                float ro0 = c[i][j][0] * t0.y + c[i][j][1] * t0.x;
                split2(re0, ro0, hh, ll);
                *(uint32_t*)(oh + (size_t)m0r * D_MODEL + col) = hh;
                *(uint32_t*)(ol + (size_t)m0r * D_MODEL + col) = ll;
                float re1 = c[i][j][2] * t1.x - c[i][j][3] * t1.y;
                float ro1 = c[i][j][2] * t1.y + c[i][j][3] * t1.x;
                split2(re1, ro1, hh, ll);
                *(uint32_t*)(oh + (size_t)m1r * D_MODEL + col) = hh;
                *(uint32_t*)(ol + (size_t)m1r * D_MODEL + col) = ll;
            }
    } else {
        // plain fp32 epilogue (V projection, or O projection when FUSED=0)
#pragma unroll
        for (int i = 0; i < 4; ++i)
#pragma unroll
            for (int j = 0; j < 4; ++j) {
                float* cp = Cf + (size_t)(row0 + wy * 64 + i * 16 + r) * Ndim
                              + col0 + wx * 32 + j * 8 + cc;
                *(float2*)cp = make_float2(c[i][j][0], c[i][j][1]);
                *(float2*)(cp + 8 * (size_t)Ndim) = make_float2(c[i][j][2], c[i][j][3]);
            }
    }
}

// ---------------------------------------------------------------------------
// V transpose + split: fp32 [b*S+t][1024] -> vth/vtl [(b*16+h)*64+d][S]
// ---------------------------------------------------------------------------
__global__ void __launch_bounds__(256) vtrans_split_kernel(
    const float* __restrict__ v,
    __nv_bfloat16* __restrict__ vth, __nv_bfloat16* __restrict__ vtl)
{
    __shared__ float tile[64][65];
    const int tb = blockIdx.x;
    const int bh = blockIdx.y;
    const int b  = bh >> 4, h = bh & 15;
    const int tid = threadIdx.x;

#pragma unroll
    for (int i = 0; i < 4; ++i) {
        int e = tid + i * 256;
        int t = e >> 4;
        int d4 = (e & 15) * 4;
        float4 vv = *(const float4*)(v + (size_t)(b * SS + tb * 64 + t) * D_MODEL
                                       + h * DK + d4);
        tile[d4 + 0][t] = vv.x;
        tile[d4 + 1][t] = vv.y;
        tile[d4 + 2][t] = vv.z;
        tile[d4 + 3][t] = vv.w;
    }
    __syncthreads();

#pragma unroll
    for (int i = 0; i < 8; ++i) {
        int e = tid + i * 256;
        int d = e >> 5;
        int t2 = (e & 31) * 2;
        uint32_t hh, ll;
        split2(tile[d][t2], tile[d][t2 + 1], hh, ll);
        size_t dst = ((size_t)(bh * 64 + d)) * SS + tb * 64 + t2;
        *(uint32_t*)(vth + dst) = hh;
        *(uint32_t*)(vtl + dst) = ll;
    }
}

// ---------------------------------------------------------------------------
// Tensor-core flash attention (causal), bf16x3. Epilogue writes bf16 hi/lo
// (feeds O-projection directly). Mainloop unchanged (validated R5).
// ---------------------------------------------------------------------------
__global__ void __launch_bounds__(256, 1) attn_tc_kernel(
    const __nv_bfloat16* __restrict__ Qh, const __nv_bfloat16* __restrict__ Ql,
    const __nv_bfloat16* __restrict__ Kh, const __nv_bfloat16* __restrict__ Kl,
    const __nv_bfloat16* __restrict__ Vth, const __nv_bfloat16* __restrict__ Vtl,
    __nv_bfloat16* __restrict__ Oh, __nv_bfloat16* __restrict__ Ol)
{
    extern __shared__ uint32_t dsm[];   // 16384 u32 = 64KB

    const int qi  = blockIdx.x;
    const int h   = blockIdx.y;
    const int b   = blockIdx.z;
    const int tid = threadIdx.x;
    const int lane = tid & 31;
    const int w    = tid >> 5;

    const int tok0 = b * SS + qi * 128;
    const int hoff = h * DK;
    const size_t vrow0 = (size_t)((b * 16 + h) * 64) * SS;
    const int kt_last = qi * 2 + 1;

#pragma unroll
    for (int i = 0; i < 8; ++i) {
        int c   = tid + i * 256;
        int arr = c >> 10;
        int cc  = c & 1023;
        int m = cc >> 3, kq = cc & 7;
        int wd = ((((m >> 4) * 4 + (kq >> 1)) * 4 + ((m >> 3) & 1) + 2 * (kq & 1)) << 5)
                 + (m & 7) * 4;
        const __nv_bfloat16* src = (arr ? Ql : Qh)
            + (size_t)(tok0 + m) * D_MODEL + hoff + kq * 8;
        CP_ASYNC16(smem_u32(dsm + 8192 + arr * 4096 + wd), src);
    }
    {
        const int kt = 0, sb = 0;
#pragma unroll
        for (int i = 0; i < 8; ++i) {
            int c = tid + i * 256;
            if (c < 1024) {
                int arr = c >> 9, cc = c & 511;
                int t = cc >> 3, kq = cc & 7;
                int wd = ((((t >> 3) * 4 + (kq >> 1)) * 2 + (kq & 1)) << 5) + (t & 7) * 4;
                const __nv_bfloat16* src = (arr ? Kl : Kh)
                    + (size_t)(b * SS + kt * 64 + t) * D_MODEL + hoff + kq * 8;
                CP_ASYNC16(smem_u32(dsm + sb + arr * 2048 + wd), src);
            } else {
                int c2 = c - 1024;
                int arr = c2 >> 9, cc = c2 & 511;
                int d = cc >> 3, tq = cc & 7;
                int wd = ((((d >> 3) * 4 + (tq >> 1)) * 2 + (tq & 1)) << 5) + (d & 7) * 4;
                const __nv_bfloat16* src = (arr ? Vtl : Vth)
                    + vrow0 + (size_t)d * SS + kt * 64 + tq * 8;
                CP_ASYNC16(smem_u32(dsm + sb + 4096 + arr * 2048 + wd), src);
            }
        }
    }
    CP_COMMIT();
    CP_WAIT0();
    __syncthreads();

    uint32_t qfh[4][4], qfl[4][4];
#pragma unroll
    for (int ks = 0; ks < 4; ++ks)
#pragma unroll
        for (int r = 0; r < 4; ++r) {
            int wd = (((w * 4 + ks) * 4 + r) << 5) + lane;
            qfh[ks][r] = dsm[8192 + wd];
            qfl[ks][r] = dsm[12288 + wd];
        }
    __syncthreads();

    float acc[8][4];
#pragma unroll
    for (int j = 0; j < 8; ++j)
#pragma unroll
        for (int r = 0; r < 4; ++r) acc[j][r] = 0.f;
    float m0 = -1e30f, m1 = -1e30f, l0 = 0.f, l1 = 0.f;

    const int q0w = qi * 128 + w * 16;

    for (int kt = 0; kt <= kt_last; ++kt) {
        const int sb = (kt & 1) * 8192;
        if (kt < kt_last) {
            const int nkt = kt + 1;
            const int nsb = (nkt & 1) * 8192;
#pragma unroll
            for (int i = 0; i < 8; ++i) {
                int c = tid + i * 256;
                if (c < 1024) {
                    int arr = c >> 9, cc = c & 511;
                    int t = cc >> 3, kq = cc & 7;
                    int wd = ((((t >> 3) * 4 + (kq >> 1)) * 2 + (kq & 1)) << 5) + (t & 7) * 4;
                    const __nv_bfloat16* src = (arr ? Kl : Kh)
                        + (size_t)(b * SS + nkt * 64 + t) * D_MODEL + hoff + kq * 8;
                    CP_ASYNC16(smem_u32(dsm + nsb + arr * 2048 + wd), src);
                } else {
                    int c2 = c - 1024;
                    int arr = c2 >> 9, cc = c2 & 511;
                    int d = cc >> 3, tq = cc & 7;
                    int wd = ((((d >> 3) * 4 + (tq >> 1)) * 2 + (tq & 1)) << 5) + (d & 7) * 4;
                    const __nv_bfloat16* src = (arr ? Vtl : Vth)
                        + vrow0 + (size_t)d * SS + nkt * 64 + tq * 8;
                    CP_ASYNC16(smem_u32(dsm + nsb + 4096 + arr * 2048 + wd), src);
                }
            }
            CP_COMMIT();
            CP_WAIT1();
        } else {
            CP_WAIT0();
        }
        __syncthreads();

        if (kt * 64 <= q0w + 15) {
            const uint32_t* sKh = dsm + sb;
            const uint32_t* sKl = dsm + sb + 2048;
            const uint32_t* sVh = dsm + sb + 4096;
            const uint32_t* sVl = dsm + sb + 6144;

            float s[8][4];
#pragma unroll
            for (int j = 0; j < 8; ++j)
#pragma unroll
                for (int r = 0; r < 4; ++r) s[j][r] = 0.f;

#pragma unroll
            for (int ks = 0; ks < 4; ++ks)
#pragma unroll
                for (int jn = 0; jn < 8; ++jn) {
                    int base = ((jn * 4 + ks) << 6) + lane;
                    uint32_t bh[2] = {sKh[base], sKh[base + 32]};
                    uint32_t bl[2] = {sKl[base], sKl[base + 32]};
                    mma_bf16(s[jn], qfh[ks], bh);
                    mma_bf16(s[jn], qfh[ks], bl);
                    mma_bf16(s[jn], qfl[ks], bh);
                }

#pragma unroll
            for (int j = 0; j < 8; ++j)
#pragma unroll
                for (int r = 0; r < 4; ++r) s[j][r] *= 0.125f;

            if (kt * 64 + 63 > q0w) {
                const int row0g = q0w + (lane >> 2);
                const int colbg = kt * 64 + 2 * (lane & 3);
#pragma unroll
                for (int jn = 0; jn < 8; ++jn) {
                    int c0 = colbg + jn * 8;
                    if (c0 > row0g)     s[jn][0] = -1e30f;
                    if (c0 + 1 > row0g) s[jn][1] = -1e30f;
                    if (c0 > row0g + 8)     s[jn][2] = -1e30f;
                    if (c0 + 1 > row0g + 8) s[jn][3] = -1e30f;
                }
            }

            float mx0 = -1e30f, mx1 = -1e30f;
#pragma unroll
            for (int j = 0; j < 8; ++j) {
                mx0 = fmaxf(mx0, fmaxf(s[j][0], s[j][1]));
                mx1 = fmaxf(mx1, fmaxf(s[j][2], s[j][3]));
            }
            mx0 = fmaxf(mx0, __shfl_xor_sync(0xffffffffu, mx0, 1));
            mx0 = fmaxf(mx0, __shfl_xor_sync(0xffffffffu, mx0, 2));
            mx1 = fmaxf(mx1, __shfl_xor_sync(0xffffffffu, mx1, 1));
            mx1 = fmaxf(mx1, __shfl_xor_sync(0xffffffffu, mx1, 2));

            float mn0 = fmaxf(m0, mx0), mn1 = fmaxf(m1, mx1);
            float al0 = __expf(m0 - mn0), al1 = __expf(m1 - mn1);
            m0 = mn0; m1 = mn1;

            float sum0 = 0.f, sum1 = 0.f;
#pragma unroll
            for (int j = 0; j < 8; ++j) {
                s[j][0] = __expf(s[j][0] - mn0);
                s[j][1] = __expf(s[j][1] - mn0);
                s[j][2] = __expf(s[j][2] - mn1);
                s[j][3] = __expf(s[j][3] - mn1);
                sum0 += s[j][0] + s[j][1];
                sum1 += s[j][2] + s[j][3];
            }
            sum0 += __shfl_xor_sync(0xffffffffu, sum0, 1);
            sum0 += __shfl_xor_sync(0xffffffffu, sum0, 2);
            sum1 += __shfl_xor_sync(0xffffffffu, sum1, 1);
            sum1 += __shfl_xor_sync(0xffffffffu, sum1, 2);
            l0 = l0 * al0 + sum0;
            l1 = l1 * al1 + sum1;

#pragma unroll
            for (int j = 0; j < 8; ++j) {
                acc[j][0] *= al0; acc[j][1] *= al0;
                acc[j][2] *= al1; acc[j][3] *= al1;
            }

            uint32_t ph[4][4], pl[4][4];
#pragma unroll
            for (int kk = 0; kk < 4; ++kk) {
                split2(s[2 * kk][0],     s[2 * kk][1],     ph[kk][0], pl[kk][0]);
                split2(s[2 * kk][2],     s[2 * kk][3],     ph[kk][1], pl[kk][1]);
                split2(s[2 * kk + 1][0], s[2 * kk + 1][1], ph[kk][2], pl[kk][2]);
                split2(s[2 * kk + 1][2], s[2 * kk + 1][3], ph[kk][3], pl[kk][3]);
            }

#pragma unroll
            for (int kk = 0; kk < 4; ++kk)
#pragma unroll
                for (int jd = 0; jd < 8; ++jd) {
                    int base = ((jd * 4 + kk) << 6) + lane;
                    uint32_t vh[2] = {sVh[base], sVh[base + 32]};
                    uint32_t vl[2] = {sVl[base], sVl[base + 32]};
                    mma_bf16(acc[jd], ph[kk], vh);
                    mma_bf16(acc[jd], ph[kk], vl);
                    mma_bf16(acc[jd], pl[kk], vh);
                }
        }
        __syncthreads();
    }

    // epilogue: normalize + split to bf16 hi/lo (input of O-projection)
    const float inv0 = 1.f / l0, inv1 = 1.f / l1;
    const int r  = lane >> 2;
    const int cc = 2 * (lane & 3);
    const size_t r0 = (size_t)(tok0 + w * 16 + r) * D_MODEL + hoff;
    const size_t r1 = r0 + 8 * (size_t)D_MODEL;
#pragma unroll
    for (int jd = 0; jd < 8; ++jd) {
        uint32_t hh, ll;
        split2(acc[jd][0] * inv0, acc[jd][1] * inv0, hh, ll);
        *(uint32_t*)(Oh + r0 + jd * 8 + cc) = hh;
        *(uint32_t*)(Ol + r0 + jd * 8 + cc) = ll;
        split2(acc[jd][2] * inv1, acc[jd][3] * inv1, hh, ll);
        *(uint32_t*)(Oh + r1 + jd * 8 + cc) = hh;
        *(uint32_t*)(Ol + r1 + jd * 8 + cc) = ll;
    }
}

// ---------------------------------------------------------------------------
extern "C" void kernel_launch(void* const* d_in, const int* in_sizes, int n_in,
                              void* d_out, int out_size)
{
    const float* wq  = (const float*)d_in[0];
    const float* wk  = (const float*)d_in[1];
    const float* wv  = (const float*)d_in[2];
    const float* wo  = (const float*)d_in[3];
    const float* x   = (const float*)d_in[4];
    const int*   pos = (const int*)d_in[5];
    float* out = (float*)d_out;

    float* dv;
    cudaGetSymbolAddress((void**)&dv, g_v);
    __nv_bfloat16 *xh, *xl, *ath, *atl, *wh, *wl;
    __nv_bfloat16 *qh, *ql, *kh, *kl, *vth, *vtl;
    float2* ropet;
    cudaGetSymbolAddress((void**)&xh,  g_xh);
    cudaGetSymbolAddress((void**)&xl,  g_xl);
    cudaGetSymbolAddress((void**)&ath, g_ah);
    cudaGetSymbolAddress((void**)&atl, g_al);
    cudaGetSymbolAddress((void**)&wh,  g_wh);
    cudaGetSymbolAddress((void**)&wl,  g_wl);
    cudaGetSymbolAddress((void**)&qh,  g_qh);
    cudaGetSymbolAddress((void**)&ql,  g_ql);
    cudaGetSymbolAddress((void**)&kh,  g_kh);
    cudaGetSymbolAddress((void**)&kl,  g_kl);
    cudaGetSymbolAddress((void**)&vth, g_vth);
    cudaGetSymbolAddress((void**)&vtl, g_vtl);
    cudaGetSymbolAddress((void**)&ropet, g_rope);

    const size_t WSZ = (size_t)D_MODEL * D_MODEL;
    const int n4x = (int)((size_t)MM * D_MODEL / 4);
    const int n4w = (int)(WSZ / 4);

    rope_table_kernel<<<(SS * HALF) / 256, 256>>>(pos, ropet);
    split_bf16_kernel<<<(n4x + 255) / 256, 256>>>(x, xh, xl, n4x);
    split_bf16_kernel<<<(n4w + 255) / 256, 256>>>(wq, wh + 0 * WSZ, wl + 0 * WSZ, n4w);
    split_bf16_kernel<<<(n4w + 255) / 256, 256>>>(wk, wh + 1 * WSZ, wl + 1 * WSZ, n4w);
    split_bf16_kernel<<<(n4w + 255) / 256, 256>>>(wv, wh + 2 * WSZ, wl + 2 * WSZ, n4w);
    split_bf16_kernel<<<(n4w + 255) / 256, 256>>>(wo, wh + 3 * WSZ, wl + 3 * WSZ, n4w);

    cudaFuncSetAttribute(gemm_bf16x3_nt<1>,
                         cudaFuncAttributeMaxDynamicSharedMemorySize, 65536);
    cudaFuncSetAttribute(gemm_bf16x3_nt<0>,
                         cudaFuncAttributeMaxDynamicSharedMemorySize, 65536);

    // fused QKV: z=0 -> rope-split q, z=1 -> rope-split k, z=2 -> fp32 v
    gemm_bf16x3_nt<1><<<dim3(D_MODEL / 128, MM / 128, 3), 256, 65536>>>(
        xh, xl, wh, wl, dv, qh, ql, kh, kl, ropet, MM, D_MODEL, D_MODEL);

    vtrans_split_kernel<<<dim3(SS / 64, BB * NUM_HEADS), 256>>>(dv, vth, vtl);

    cudaFuncSetAttribute(attn_tc_kernel,
                         cudaFuncAttributeMaxDynamicSharedMemorySize, 65536);
    attn_tc_kernel<<<dim3(SS / 128, NUM_HEADS, BB), 256, 65536>>>(
        qh, ql, kh, kl, vth, vtl, ath, atl);

    // O projection: plain fp32 epilogue, weight slot 3
    gemm_bf16x3_nt<0><<<dim3(D_MODEL / 128, MM / 128, 1), 256, 65536>>>(
        ath, atl, wh + 3 * WSZ, wl + 3 * WSZ, out,
        nullptr, nullptr, nullptr, nullptr, ropet, MM, D_MODEL, D_MODEL);
}

// round 9
// speedup vs baseline: 2.5476x; 1.0215x over previous
#include <cuda_runtime.h>
#include <cuda_bf16.h>
#include <math.h>
#include <stdint.h>

#define D_MODEL 1024
#define NUM_HEADS 16
#define DK 64
#define HALF 32
#define BB 4
#define SS 2048
#define MM (BB * SS)           // 8192 tokens
#define LOG2_THETA 13.287712379549449f   // log2(10000)

// ---------------- scratch (device globals: no allocation allowed) ----------
__device__ float g_v[(size_t)MM * D_MODEL];            // V projection (fp32)

__device__ __nv_bfloat16 g_xh[(size_t)MM * D_MODEL];
__device__ __nv_bfloat16 g_xl[(size_t)MM * D_MODEL];
__device__ __nv_bfloat16 g_ah[(size_t)MM * D_MODEL];   // attention out hi
__device__ __nv_bfloat16 g_al[(size_t)MM * D_MODEL];   // attention out lo
__device__ __nv_bfloat16 g_wh[4][(size_t)D_MODEL * D_MODEL];
__device__ __nv_bfloat16 g_wl[4][(size_t)D_MODEL * D_MODEL];

__device__ __nv_bfloat16 g_qh[(size_t)MM * D_MODEL];
__device__ __nv_bfloat16 g_ql[(size_t)MM * D_MODEL];
__device__ __nv_bfloat16 g_kh[(size_t)MM * D_MODEL];
__device__ __nv_bfloat16 g_kl[(size_t)MM * D_MODEL];
__device__ __nv_bfloat16 g_vth[(size_t)MM * D_MODEL];  // [(b*16+h)*64+d][S]
__device__ __nv_bfloat16 g_vtl[(size_t)MM * D_MODEL];

__device__ float2 g_rope[(size_t)SS * HALF];           // {cos, sin} table

// ---------------------------------------------------------------------------
__device__ __forceinline__ uint32_t smem_u32(const void* p) {
    return (uint32_t)__cvta_generic_to_shared(p);
}
#define CP_ASYNC16(dst, src) \
    asm volatile("cp.async.cg.shared.global [%0], [%1], 16;\n" :: "r"(dst), "l"(src))
#define CP_COMMIT() asm volatile("cp.async.commit_group;\n" ::: "memory")
#define CP_WAIT2()  asm volatile("cp.async.wait_group 2;\n" ::: "memory")
#define CP_WAIT1()  asm volatile("cp.async.wait_group 1;\n" ::: "memory")
#define CP_WAIT0()  asm volatile("cp.async.wait_group 0;\n" ::: "memory")

__device__ __forceinline__ void mma_bf16(float c[4], const uint32_t a[4],
                                         const uint32_t b[2]) {
    asm volatile(
        "mma.sync.aligned.m16n8k16.row.col.f32.bf16.bf16.f32 "
        "{%0,%1,%2,%3}, {%4,%5,%6,%7}, {%8,%9}, {%0,%1,%2,%3};\n"
        : "+f"(c[0]), "+f"(c[1]), "+f"(c[2]), "+f"(c[3])
        : "r"(a[0]), "r"(a[1]), "r"(a[2]), "r"(a[3]), "r"(b[0]), "r"(b[1]));
}

__device__ __forceinline__ void split2(float x, float y, uint32_t& hi, uint32_t& lo) {
    __nv_bfloat162 h = __floats2bfloat162_rn(x, y);
    float hx = __bfloat162float(h.x), hy = __bfloat162float(h.y);
    __nv_bfloat162 l = __floats2bfloat162_rn(x - hx, y - hy);
    hi = *(uint32_t*)&h;
    lo = *(uint32_t*)&l;
}

// ---------------------------------------------------------------------------
// RoPE cos/sin table: tab[s*32 + i] = {cos, sin}(pos[s] * theta^(-i/32))
// ---------------------------------------------------------------------------
__global__ void __launch_bounds__(256) rope_table_kernel(
    const int* __restrict__ pos, float2* __restrict__ tab)
{
    int idx = blockIdx.x * blockDim.x + threadIdx.x;   // < SS*HALF
    int s = idx >> 5, i = idx & (HALF - 1);
    float p = (float)pos[s];
    float inv_freq = exp2f(-(float)i * (LOG2_THETA / (float)HALF));
    float sn, cs;
    sincosf(p * inv_freq, &sn, &cs);
    tab[idx] = make_float2(cs, sn);
}

// ---------------------------------------------------------------------------
// fp32 -> (bf16 hi, bf16 lo) split (single tensor).
// ---------------------------------------------------------------------------
__global__ void __launch_bounds__(256) split_bf16_kernel(
    const float* __restrict__ src, __nv_bfloat16* __restrict__ hi,
    __nv_bfloat16* __restrict__ lo, int n4)
{
    int i = blockIdx.x * blockDim.x + threadIdx.x;
    if (i >= n4) return;
    float4 v = ((const float4*)src)[i];
    uint32_t h0, l0, h1, l1;
    split2(v.x, v.y, h0, l0);
    split2(v.z, v.w, h1, l1);
    ((uint32_t*)hi)[i * 2 + 0] = h0;
    ((uint32_t*)hi)[i * 2 + 1] = h1;
    ((uint32_t*)lo)[i * 2 + 0] = l0;
    ((uint32_t*)lo)[i * 2 + 1] = l1;
}

// 4 weight tensors in one launch (blockIdx.y selects tensor).
__global__ void __launch_bounds__(256) split4_bf16_kernel(
    const float* __restrict__ w0, const float* __restrict__ w1,
    const float* __restrict__ w2, const float* __restrict__ w3,
    __nv_bfloat16* __restrict__ hiB, __nv_bfloat16* __restrict__ loB, int n4)
{
    int i = blockIdx.x * blockDim.x + threadIdx.x;
    if (i >= n4) return;
    const int zz = blockIdx.y;
    const float* src = (zz == 0) ? w0 : (zz == 1) ? w1 : (zz == 2) ? w2 : w3;
    __nv_bfloat16* hi = hiB + (size_t)zz * D_MODEL * D_MODEL;
    __nv_bfloat16* lo = loB + (size_t)zz * D_MODEL * D_MODEL;
    float4 v = ((const float4*)src)[i];
    uint32_t h0, l0, h1, l1;
    split2(v.x, v.y, h0, l0);
    split2(v.z, v.w, h1, l1);
    ((uint32_t*)hi)[i * 2 + 0] = h0;
    ((uint32_t*)hi)[i * 2 + 1] = h1;
    ((uint32_t*)lo)[i * 2 + 0] = l0;
    ((uint32_t*)lo)[i * 2 + 1] = l1;
}

// ---------------------------------------------------------------------------
// bf16x3 mma.sync GEMM (NT), 4-stage cp.async, SINGLE sync per k-step.
// FUSED=1 (QKV): z=0 -> rope+split to qh/ql; z=1 -> rope+split to kh/kl;
//                z=2 -> fp32 to Cf (V).
// FUSED=0 (O-proj): plain fp32 epilogue to Cf.
// ---------------------------------------------------------------------------
__device__ __forceinline__ void load_stage4(
    const __nv_bfloat16* __restrict__ gAh, const __nv_bfloat16* __restrict__ gAl,
    const __nv_bfloat16* __restrict__ gBh, const __nv_bfloat16* __restrict__ gBl,
    int Kdim, int k0, uint32_t* sb, int tid)
{
    const int m = tid >> 1;
    const int q = tid & 1;
    const size_t src = (size_t)m * Kdim + k0 + q * 8;
    const int aw = ((((m >> 4) * 4 + ((m >> 3) & 1) + 2 * q)) << 5) + (m & 7) * 4;
    const int bw = ((((m >> 3) * 2 + q)) << 5) + (m & 7) * 4;
    CP_ASYNC16(smem_u32(sb + aw),        gAh + src);
    CP_ASYNC16(smem_u32(sb + 1024 + aw), gAl + src);
    CP_ASYNC16(smem_u32(sb + 2048 + bw), gBh + src);
    CP_ASYNC16(smem_u32(sb + 3072 + bw), gBl + src);
}

template <int FUSED>
__global__ void __launch_bounds__(256) gemm_bf16x3_nt(
    const __nv_bfloat16* __restrict__ Ah, const __nv_bfloat16* __restrict__ Al,
    const __nv_bfloat16* __restrict__ WhB, const __nv_bfloat16* __restrict__ WlB,
    float* __restrict__ Cf,
    __nv_bfloat16* __restrict__ qh, __nv_bfloat16* __restrict__ ql,
    __nv_bfloat16* __restrict__ kh, __nv_bfloat16* __restrict__ kl,
    const float2* __restrict__ rope,
    int Mdim, int Ndim, int Kdim)
{
    extern __shared__ uint32_t smem4[];   // 4 stages x 4096 u32 = 64KB

    const int tid  = threadIdx.x;
    const int lane = tid & 31;
    const int warp = tid >> 5;
    const int wy   = warp >> 2;
    const int wx   = warp & 3;
    const int row0 = blockIdx.y * 128;
    const int col0 = blockIdx.x * 128;
    const int z    = blockIdx.z;
    const size_t zw = (size_t)z * D_MODEL * D_MODEL;

    const __nv_bfloat16* gAh = Ah + (size_t)row0 * Kdim;
    const __nv_bfloat16* gAl = Al + (size_t)row0 * Kdim;
    const __nv_bfloat16* gBh = WhB + zw + (size_t)col0 * Kdim;
    const __nv_bfloat16* gBl = WlB + zw + (size_t)col0 * Kdim;

    float c[4][4][4];
#pragma unroll
    for (int i = 0; i < 4; ++i)
#pragma unroll
        for (int j = 0; j < 4; ++j)
#pragma unroll
            for (int r = 0; r < 4; ++r) c[i][j][r] = 0.f;

    const int NT = Kdim / 16;             // 64
    load_stage4(gAh, gAl, gBh, gBl, Kdim, 0,  smem4,        tid); CP_COMMIT();
    load_stage4(gAh, gAl, gBh, gBl, Kdim, 16, smem4 + 4096, tid); CP_COMMIT();
    load_stage4(gAh, gAl, gBh, gBl, Kdim, 32, smem4 + 8192, tid); CP_COMMIT();

    for (int t = 0; t < NT; ++t) {
        // stage t's group is the oldest outstanding; leave newer ones pending.
        if (t < NT - 2)      { CP_WAIT2(); }
        else if (t < NT - 1) { CP_WAIT1(); }
        else                 { CP_WAIT0(); }
        __syncthreads();   // data visibility + WAR guard for the issue below

        if (t + 3 < NT) {
            load_stage4(gAh, gAl, gBh, gBl, Kdim, (t + 3) * 16,
                        smem4 + ((t + 3) & 3) * 4096, tid);
            CP_COMMIT();
        }

        const uint32_t* sb  = smem4 + (t & 3) * 4096;
        const uint32_t* pAh = sb;
        const uint32_t* pAl = sb + 1024;
        const uint32_t* pBh = sb + 2048;
        const uint32_t* pBl = sb + 3072;

        uint32_t ah[4][4], al[4][4], bh[4][2], bl[4][2];
#pragma unroll
        for (int i = 0; i < 4; ++i) {
            const int base = (((wy * 4 + i) * 4) << 5) + lane;
#pragma unroll
            for (int r = 0; r < 4; ++r) {
                ah[i][r] = pAh[base + (r << 5)];
                al[i][r] = pAl[base + (r << 5)];
            }
        }
#pragma unroll
        for (int j = 0; j < 4; ++j) {
            const int base = (((wx * 4 + j) * 2) << 5) + lane;
#pragma unroll
            for (int r = 0; r < 2; ++r) {
                bh[j][r] = pBh[base + (r << 5)];
                bl[j][r] = pBl[base + (r << 5)];
            }
        }

#pragma unroll
        for (int i = 0; i < 4; ++i)
#pragma unroll
            for (int j = 0; j < 4; ++j) {
                mma_bf16(c[i][j], ah[i], bh[j]);
                mma_bf16(c[i][j], ah[i], bl[j]);
                mma_bf16(c[i][j], al[i], bh[j]);
            }
        // no trailing sync: next iteration's leading sync is the WAR guard
    }

    const int r  = lane >> 2;
    const int cc = (lane & 3) * 2;

    if (FUSED && z < 2) {
        __nv_bfloat16* oh = z ? kh : qh;
        __nv_bfloat16* ol = z ? kl : ql;
#pragma unroll
        for (int i = 0; i < 4; ++i)
#pragma unroll
            for (int j = 0; j < 4; ++j) {
                const int col = col0 + wx * 32 + j * 8 + cc;       // even
                const int pi  = (col & 63) >> 1;                   // rope pair idx
                const int m0r = row0 + wy * 64 + i * 16 + r;
                const int m1r = m0r + 8;
                float2 t0 = rope[(size_t)(m0r & (SS - 1)) * HALF + pi];
                float2 t1 = rope[(size_t)(m1r & (SS - 1)) * HALF + pi];
                uint32_t hh, ll;
                float re0 = c[i][j][0] * t0.x - c[i][j][1] * t0.y;
                float ro0 = c[i][j][0] * t0.y + c[i][j][1] * t0.x;
                split2(re0, ro0, hh, ll);
                *(uint32_t*)(oh + (size_t)m0r * D_MODEL + col) = hh;
                *(uint32_t*)(ol + (size_t)m0r * D_MODEL + col) = ll;
                float re1 = c[i][j][2] * t1.x - c[i][j][3] * t1.y;
                float ro1 = c[i][j][2] * t1.y + c[i][j][3] * t1.x;
                split2(re1, ro1, hh, ll);
                *(uint32_t*)(oh + (size_t)m1r * D_MODEL + col) = hh;
                *(uint32_t*)(ol + (size_t)m1r * D_MODEL + col) = ll;
            }
    } else {
#pragma unroll
        for (int i = 0; i < 4; ++i)
#pragma unroll
            for (int j = 0; j < 4; ++j) {
                float* cp = Cf + (size_t)(row0 + wy * 64 + i * 16 + r) * Ndim
                              + col0 + wx * 32 + j * 8 + cc;
                *(float2*)cp = make_float2(c[i][j][0], c[i][j][1]);
                *(float2*)(cp + 8 * (size_t)Ndim) = make_float2(c[i][j][2], c[i][j][3]);
            }
    }
}

// ---------------------------------------------------------------------------
// V transpose + split: fp32 [b*S+t][1024] -> vth/vtl [(b*16+h)*64+d][S]
// ---------------------------------------------------------------------------
__global__ void __launch_bounds__(256) vtrans_split_kernel(
    const float* __restrict__ v,
    __nv_bfloat16* __restrict__ vth, __nv_bfloat16* __restrict__ vtl)
{
    __shared__ float tile[64][65];
    const int tb = blockIdx.x;
    const int bh = blockIdx.y;
    const int b  = bh >> 4, h = bh & 15;
    const int tid = threadIdx.x;

#pragma unroll
    for (int i = 0; i < 4; ++i) {
        int e = tid + i * 256;
        int t = e >> 4;
        int d4 = (e & 15) * 4;
        float4 vv = *(const float4*)(v + (size_t)(b * SS + tb * 64 + t) * D_MODEL
                                       + h * DK + d4);
        tile[d4 + 0][t] = vv.x;
        tile[d4 + 1][t] = vv.y;
        tile[d4 + 2][t] = vv.z;
        tile[d4 + 3][t] = vv.w;
    }
    __syncthreads();

#pragma unroll
    for (int i = 0; i < 8; ++i) {
        int e = tid + i * 256;
        int d = e >> 5;
        int t2 = (e & 31) * 2;
        uint32_t hh, ll;
        split2(tile[d][t2], tile[d][t2 + 1], hh, ll);
        size_t dst = ((size_t)(bh * 64 + d)) * SS + tb * 64 + t2;
        *(uint32_t*)(vth + dst) = hh;
        *(uint32_t*)(vtl + dst) = ll;
    }
}

// ---------------------------------------------------------------------------
// Tensor-core flash attention (causal), bf16x3.
// Single sync per K-tile; big-qi blocks launched first (LPT packing).
// Epilogue writes bf16 hi/lo (feeds O-projection directly).
// ---------------------------------------------------------------------------
__device__ __forceinline__ void attn_load_tile(
    uint32_t* dsm, int nsb, int tid, int b, int kt, int hoff, size_t vrow0,
    const __nv_bfloat16* __restrict__ Kh, const __nv_bfloat16* __restrict__ Kl,
    const __nv_bfloat16* __restrict__ Vth, const __nv_bfloat16* __restrict__ Vtl)
{
#pragma unroll
    for (int i = 0; i < 8; ++i) {
        int c = tid + i * 256;
        if (c < 1024) {
            int arr = c >> 9, cc = c & 511;
            int t = cc >> 3, kq = cc & 7;
            int wd = ((((t >> 3) * 4 + (kq >> 1)) * 2 + (kq & 1)) << 5) + (t & 7) * 4;
            const __nv_bfloat16* src = (arr ? Kl : Kh)
                + (size_t)(b * SS + kt * 64 + t) * D_MODEL + hoff + kq * 8;
            CP_ASYNC16(smem_u32(dsm + nsb + arr * 2048 + wd), src);
        } else {
            int c2 = c - 1024;
            int arr = c2 >> 9, cc = c2 & 511;
            int d = cc >> 3, tq = cc & 7;
            int wd = ((((d >> 3) * 4 + (tq >> 1)) * 2 + (tq & 1)) << 5) + (d & 7) * 4;
            const __nv_bfloat16* src = (arr ? Vtl : Vth)
                + vrow0 + (size_t)d * SS + kt * 64 + tq * 8;
            CP_ASYNC16(smem_u32(dsm + nsb + 4096 + arr * 2048 + wd), src);
        }
    }
}

__global__ void __launch_bounds__(256, 1) attn_tc_kernel(
    const __nv_bfloat16* __restrict__ Qh, const __nv_bfloat16* __restrict__ Ql,
    const __nv_bfloat16* __restrict__ Kh, const __nv_bfloat16* __restrict__ Kl,
    const __nv_bfloat16* __restrict__ Vth, const __nv_bfloat16* __restrict__ Vtl,
    __nv_bfloat16* __restrict__ Oh, __nv_bfloat16* __restrict__ Ol)
{
    extern __shared__ uint32_t dsm[];   // 16384 u32 = 64KB

    const int qi  = (gridDim.x - 1) - blockIdx.x;   // big work first (LPT)
    const int h   = blockIdx.y;
    const int b   = blockIdx.z;
    const int tid = threadIdx.x;
    const int lane = tid & 31;
    const int w    = tid >> 5;

    const int tok0 = b * SS + qi * 128;
    const int hoff = h * DK;
    const size_t vrow0 = (size_t)((b * 16 + h) * 64) * SS;
    const int kt_last = qi * 2 + 1;

    // prologue: Q into stage1 region (words 8192..16383), tile0 into stage0
#pragma unroll
    for (int i = 0; i < 8; ++i) {
        int c   = tid + i * 256;
        int arr = c >> 10;
        int cc  = c & 1023;
        int m = cc >> 3, kq = cc & 7;
        int wd = ((((m >> 4) * 4 + (kq >> 1)) * 4 + ((m >> 3) & 1) + 2 * (kq & 1)) << 5)
                 + (m & 7) * 4;
        const __nv_bfloat16* src = (arr ? Ql : Qh)
            + (size_t)(tok0 + m) * D_MODEL + hoff + kq * 8;
        CP_ASYNC16(smem_u32(dsm + 8192 + arr * 4096 + wd), src);
    }
    attn_load_tile(dsm, 0, tid, b, 0, hoff, vrow0, Kh, Kl, Vth, Vtl);
    CP_COMMIT();
    CP_WAIT0();
    __syncthreads();

    uint32_t qfh[4][4], qfl[4][4];
#pragma unroll
    for (int ks = 0; ks < 4; ++ks)
#pragma unroll
        for (int r = 0; r < 4; ++r) {
            int wd = (((w * 4 + ks) * 4 + r) << 5) + lane;
            qfh[ks][r] = dsm[8192 + wd];
            qfl[ks][r] = dsm[12288 + wd];
        }
    __syncthreads();   // Q region now free (stage 1 overlays it)

    float acc[8][4];
#pragma unroll
    for (int j = 0; j < 8; ++j)
#pragma unroll
        for (int r = 0; r < 4; ++r) acc[j][r] = 0.f;
    float m0 = -1e30f, m1 = -1e30f, l0 = 0.f, l1 = 0.f;

    const int q0w = qi * 128 + w * 16;

    for (int kt = 0; kt <= kt_last; ++kt) {
        const int sb = (kt & 1) * 8192;
        CP_WAIT0();        // loads for kt complete (overlapped compute kt-1)
        __syncthreads();   // visibility + WAR guard for the issue below

        if (kt < kt_last) {
            attn_load_tile(dsm, ((kt + 1) & 1) * 8192, tid, b, kt + 1,
                           hoff, vrow0, Kh, Kl, Vth, Vtl);
            CP_COMMIT();
        }

        if (kt * 64 <= q0w + 15) {
            const uint32_t* sKh = dsm + sb;
            const uint32_t* sKl = dsm + sb + 2048;
            const uint32_t* sVh = dsm + sb + 4096;
            const uint32_t* sVl = dsm + sb + 6144;

            float s[8][4];
#pragma unroll
            for (int j = 0; j < 8; ++j)
#pragma unroll
                for (int r = 0; r < 4; ++r) s[j][r] = 0.f;

#pragma unroll
            for (int ks = 0; ks < 4; ++ks)
#pragma unroll
                for (int jn = 0; jn < 8; ++jn) {
                    int base = ((jn * 4 + ks) << 6) + lane;
                    uint32_t bh[2] = {sKh[base], sKh[base + 32]};
                    uint32_t bl[2] = {sKl[base], sKl[base + 32]};
                    mma_bf16(s[jn], qfh[ks], bh);
                    mma_bf16(s[jn], qfh[ks], bl);
                    mma_bf16(s[jn], qfl[ks], bh);
                }

#pragma unroll
            for (int j = 0; j < 8; ++j)
#pragma unroll
                for (int r = 0; r < 4; ++r) s[j][r] *= 0.125f;

            if (kt * 64 + 63 > q0w) {
                const int row0g = q0w + (lane >> 2);
                const int colbg = kt * 64 + 2 * (lane & 3);
#pragma unroll
                for (int jn = 0; jn < 8; ++jn) {
                    int c0 = colbg + jn * 8;
                    if (c0 > row0g)     s[jn][0] = -1e30f;
                    if (c0 + 1 > row0g) s[jn][1] = -1e30f;
                    if (c0 > row0g + 8)     s[jn][2] = -1e30f;
                    if (c0 + 1 > row0g + 8) s[jn][3] = -1e30f;
                }
            }

            float mx0 = -1e30f, mx1 = -1e30f;
#pragma unroll
            for (int j = 0; j < 8; ++j) {
                mx0 = fmaxf(mx0, fmaxf(s[j][0], s[j][1]));
                mx1 = fmaxf(mx1, fmaxf(s[j][2], s[j][3]));
            }
            mx0 = fmaxf(mx0, __shfl_xor_sync(0xffffffffu, mx0, 1));
            mx0 = fmaxf(mx0, __shfl_xor_sync(0xffffffffu, mx0, 2));
            mx1 = fmaxf(mx1, __shfl_xor_sync(0xffffffffu, mx1, 1));
            mx1 = fmaxf(mx1, __shfl_xor_sync(0xffffffffu, mx1, 2));

            float mn0 = fmaxf(m0, mx0), mn1 = fmaxf(m1, mx1);
            float al0 = __expf(m0 - mn0), al1 = __expf(m1 - mn1);
            m0 = mn0; m1 = mn1;

            float sum0 = 0.f, sum1 = 0.f;
#pragma unroll
            for (int j = 0; j < 8; ++j) {
                s[j][0] = __expf(s[j][0] - mn0);
                s[j][1] = __expf(s[j][1] - mn0);
                s[j][2] = __expf(s[j][2] - mn1);
                s[j][3] = __expf(s[j][3] - mn1);
                sum0 += s[j][0] + s[j][1];
                sum1 += s[j][2] + s[j][3];
            }
            sum0 += __shfl_xor_sync(0xffffffffu, sum0, 1);
            sum0 += __shfl_xor_sync(0xffffffffu, sum0, 2);
            sum1 += __shfl_xor_sync(0xffffffffu, sum1, 1);
            sum1 += __shfl_xor_sync(0xffffffffu, sum1, 2);
            l0 = l0 * al0 + sum0;
            l1 = l1 * al1 + sum1;

#pragma unroll
            for (int j = 0; j < 8; ++j) {
                acc[j][0] *= al0; acc[j][1] *= al0;
                acc[j][2] *= al1; acc[j][3] *= al1;
            }

            uint32_t ph[4][4], pl[4][4];
#pragma unroll
            for (int kk = 0; kk < 4; ++kk) {
                split2(s[2 * kk][0],     s[2 * kk][1],     ph[kk][0], pl[kk][0]);
                split2(s[2 * kk][2],     s[2 * kk][3],     ph[kk][1], pl[kk][1]);
                split2(s[2 * kk + 1][0], s[2 * kk + 1][1], ph[kk][2], pl[kk][2]);
                split2(s[2 * kk + 1][2], s[2 * kk + 1][3], ph[kk][3], pl[kk][3]);
            }

#pragma unroll
            for (int kk = 0; kk < 4; ++kk)
#pragma unroll
                for (int jd = 0; jd < 8; ++jd) {
                    int base = ((jd * 4 + kk) << 6) + lane;
                    uint32_t vh[2] = {sVh[base], sVh[base + 32]};
                    uint32_t vl[2] = {sVl[base], sVl[base + 32]};
                    mma_bf16(acc[jd], ph[kk], vh);
                    mma_bf16(acc[jd], ph[kk], vl);
                    mma_bf16(acc[jd], pl[kk], vh);
                }
        }
        // no trailing sync: next iteration's leading sync is the WAR guard
    }

    // epilogue: normalize + split to bf16 hi/lo (input of O-projection)
    const float inv0 = 1.f / l0, inv1 = 1.f / l1;
    const int r  = lane >> 2;
    const int cc = 2 * (lane & 3);
    const size_t r0 = (size_t)(tok0 + w * 16 + r) * D_MODEL + hoff;
    const size_t r1 = r0 + 8 * (size_t)D_MODEL;
#pragma unroll
    for (int jd = 0; jd < 8; ++jd) {
        uint32_t hh, ll;
        split2(acc[jd][0] * inv0, acc[jd][1] * inv0, hh, ll);
        *(uint32_t*)(Oh + r0 + jd * 8 + cc) = hh;
        *(uint32_t*)(Ol + r0 + jd * 8 + cc) = ll;
        split2(acc[jd][2] * inv1, acc[jd][3] * inv1, hh, ll);
        *(uint32_t*)(Oh + r1 + jd * 8 + cc) = hh;
        *(uint32_t*)(Ol + r1 + jd * 8 + cc) = ll;
    }
}

// ---------------------------------------------------------------------------
extern "C" void kernel_launch(void* const* d_in, const int* in_sizes, int n_in,
                              void* d_out, int out_size)
{
    const float* wq  = (const float*)d_in[0];
    const float* wk  = (const float*)d_in[1];
    const float* wv  = (const float*)d_in[2];
    const float* wo  = (const float*)d_in[3];
    const float* x   = (const float*)d_in[4];
    const int*   pos = (const int*)d_in[5];
    float* out = (float*)d_out;

    float* dv;
    cudaGetSymbolAddress((void**)&dv, g_v);
    __nv_bfloat16 *xh, *xl, *ath, *atl, *wh, *wl;
    __nv_bfloat16 *qh, *ql, *kh, *kl, *vth, *vtl;
    float2* ropet;
    cudaGetSymbolAddress((void**)&xh,  g_xh);
    cudaGetSymbolAddress((void**)&xl,  g_xl);
    cudaGetSymbolAddress((void**)&ath, g_ah);
    cudaGetSymbolAddress((void**)&atl, g_al);
    cudaGetSymbolAddress((void**)&wh,  g_wh);
    cudaGetSymbolAddress((void**)&wl,  g_wl);
    cudaGetSymbolAddress((void**)&qh,  g_qh);
    cudaGetSymbolAddress((void**)&ql,  g_ql);
    cudaGetSymbolAddress((void**)&kh,  g_kh);
    cudaGetSymbolAddress((void**)&kl,  g_kl);
    cudaGetSymbolAddress((void**)&vth, g_vth);
    cudaGetSymbolAddress((void**)&vtl, g_vtl);
    cudaGetSymbolAddress((void**)&ropet, g_rope);

    const size_t WSZ = (size_t)D_MODEL * D_MODEL;
    const int n4x = (int)((size_t)MM * D_MODEL / 4);
    const int n4w = (int)(WSZ / 4);

    rope_table_kernel<<<(SS * HALF) / 256, 256>>>(pos, ropet);
    split_bf16_kernel<<<(n4x + 255) / 256, 256>>>(x, xh, xl, n4x);
    split4_bf16_kernel<<<dim3((n4w + 255) / 256, 4), 256>>>(
        wq, wk, wv, wo, wh, wl, n4w);

    cudaFuncSetAttribute(gemm_bf16x3_nt<1>,
                         cudaFuncAttributeMaxDynamicSharedMemorySize, 65536);
    cudaFuncSetAttribute(gemm_bf16x3_nt<0>,
                         cudaFuncAttributeMaxDynamicSharedMemorySize, 65536);

    // fused QKV: z=0 -> rope-split q, z=1 -> rope-split k, z=2 -> fp32 v
    gemm_bf16x3_nt<1><<<dim3(D_MODEL / 128, MM / 128, 3), 256, 65536>>>(
        xh, xl, wh, wl, dv, qh, ql, kh, kl, ropet, MM, D_MODEL, D_MODEL);

    vtrans_split_kernel<<<dim3(SS / 64, BB * NUM_HEADS), 256>>>(dv, vth, vtl);

    cudaFuncSetAttribute(attn_tc_kernel,
                         cudaFuncAttributeMaxDynamicSharedMemorySize, 65536);
    attn_tc_kernel<<<dim3(SS / 128, NUM_HEADS, BB), 256, 65536>>>(
        qh, ql, kh, kl, vth, vtl, ath, atl);

    // O projection: plain fp32 epilogue, weight slot 3
    gemm_bf16x3_nt<0><<<dim3(D_MODEL / 128, MM / 128, 1), 256, 65536>>>(
        ath, atl, wh + 3 * WSZ, wl + 3 * WSZ, out,
        nullptr, nullptr, nullptr, nullptr, ropet, MM, D_MODEL, D_MODEL);
}